// round 2
// baseline (speedup 1.0000x reference)
#include <cuda_runtime.h>
#include <math.h>

// Problem constants (fixed by the reference).
#define N_TOK  65536
#define NSPEC  4
#define D_IN   256
#define D_HID  1024
#define D_OUT  256

// ---------------------------------------------------------------------------
// Device-global scratch (allocation-free rule: __device__ arrays only).
// ---------------------------------------------------------------------------
__device__ int   g_cnt[NSPEC];
__device__ int   g_or_odd;                      // dtype probe accumulator
__device__ int   g_idx[NSPEC * N_TOK];          // bucketed token ids per species
__device__ float g_H[(size_t)N_TOK * D_HID];    // hidden activations, token-indexed

// ---------------------------------------------------------------------------
// Routing. Species dtype is ambiguous (jnp.int64 request, but JAX x64-off
// emits int32). Probe: safe region = first 65536 int32 words (covers both
// layouts). If int64 w/ values 0..3, ALL odd words are 0; if int32 random
// 0..3, some odd word is nonzero w.p. 1 - 4^-32768.
// ---------------------------------------------------------------------------
__global__ void k_reset() {
    if (threadIdx.x < NSPEC) g_cnt[threadIdx.x] = 0;
    if (threadIdx.x == 0)    g_or_odd = 0;
}

__global__ void k_probe(const int* __restrict__ w) {
    int i = blockIdx.x * blockDim.x + threadIdx.x;   // odd-word index 0..32767
    int v = w[2 * i + 1];
    // warp-reduce OR, then one atomic per warp
    for (int o = 16; o > 0; o >>= 1) v |= __shfl_xor_sync(0xffffffffu, v, o);
    if ((threadIdx.x & 31) == 0 && v) atomicOr(&g_or_odd, 1);
}

__global__ void k_scatter(const int* __restrict__ w) {
    int i = blockIdx.x * blockDim.x + threadIdx.x;
    if (i >= N_TOK) return;
    bool is64 = (g_or_odd == 0);                 // all odd words zero -> int64
    int s = is64 ? w[2 * i] : w[i];              // little-endian low word
    if ((unsigned)s < NSPEC) {                   // guard: never corrupt scratch
        int p = atomicAdd(&g_cnt[s], 1);
        g_idx[s * N_TOK + p] = i;
    }
}

// ---------------------------------------------------------------------------
// Tiled fp32 GEMM over one species bucket.
//   C[tok] = act( A[tok] @ B[s] + bias[s] )
// A: [N_TOK, KDIM] token-indexed rows, gathered through g_idx.
// B: [NSPEC, KDIM, NDIM] row-major.  C: [N_TOK, NDIM] token-indexed rows.
// Block tile 128(M) x 128(N) x 8(K); 256 threads; 8x8 per-thread microtile.
// ---------------------------------------------------------------------------
template<int KDIM, int NDIM, bool SILU>
__global__ __launch_bounds__(256, 2)
void mlp_gemm(const float* __restrict__ A,
              const float* __restrict__ B,
              const float* __restrict__ bias,
              float*       __restrict__ C)
{
    const int s   = blockIdx.z;
    const int cnt = g_cnt[s];
    const int m0  = blockIdx.x * 128;
    if (m0 >= cnt) return;
    const int n0    = blockIdx.y * 128;
    const int valid = min(128, cnt - m0);
    const int tid   = threadIdx.x;

    __shared__ float As[8][132];
    __shared__ float Bs[8][128];
    __shared__ int   tok[128];

    for (int i = tid; i < 128; i += 256)
        tok[i] = (i < valid) ? g_idx[s * N_TOK + m0 + i] : -1;
    __syncthreads();

    const float* Bsp = B + (size_t)s * KDIM * NDIM + n0;

    float acc[8][8];
#pragma unroll
    for (int i = 0; i < 8; i++)
#pragma unroll
        for (int j = 0; j < 8; j++) acc[i][j] = 0.f;

    const int tx = tid & 15;          // n microtile
    const int ty = tid >> 4;          // m microtile

    const int arow  = tid >> 1;       // 0..127  (A gather row)
    const int acol4 = (tid & 1) * 4;  // which half of the 8-wide k slice
    const int brow  = tid >> 5;       // 0..7    (B k row)
    const int bcol4 = (tid & 31) * 4; // 0..124  (B n column, float4)

    const int atok = tok[arow];
    const float* Arow = (atok >= 0) ? (A + (size_t)atok * KDIM) : nullptr;

    for (int kt = 0; kt < KDIM; kt += 8) {
        float4 av = make_float4(0.f, 0.f, 0.f, 0.f);
        if (Arow) av = *(const float4*)(Arow + kt + acol4);
        As[acol4 + 0][arow] = av.x;
        As[acol4 + 1][arow] = av.y;
        As[acol4 + 2][arow] = av.z;
        As[acol4 + 3][arow] = av.w;

        *(float4*)&Bs[brow][bcol4] =
            *(const float4*)(Bsp + (size_t)(kt + brow) * NDIM + bcol4);
        __syncthreads();

#pragma unroll
        for (int kk = 0; kk < 8; kk++) {
            float a[8], b[8];
            *(float4*)&a[0] = *(const float4*)&As[kk][ty * 8];
            *(float4*)&a[4] = *(const float4*)&As[kk][ty * 8 + 4];
            *(float4*)&b[0] = *(const float4*)&Bs[kk][tx * 8];
            *(float4*)&b[4] = *(const float4*)&Bs[kk][tx * 8 + 4];
#pragma unroll
            for (int i = 0; i < 8; i++)
#pragma unroll
                for (int j = 0; j < 8; j++)
                    acc[i][j] = fmaf(a[i], b[j], acc[i][j]);
        }
        __syncthreads();
    }

    // Epilogue: bias, optional SiLU, scatter rows back by token id.
    float bv[8];
#pragma unroll
    for (int j = 0; j < 8; j++) bv[j] = bias[s * NDIM + n0 + tx * 8 + j];

#pragma unroll
    for (int i = 0; i < 8; i++) {
        int m = ty * 8 + i;
        if (m >= valid) continue;
        int t = tok[m];
        float* cp = C + (size_t)t * NDIM + n0 + tx * 8;
#pragma unroll
        for (int j = 0; j < 8; j++) {
            float v = acc[i][j] + bv[j];
            if (SILU) v = v / (1.f + expf(-v));
            cp[j] = v;
        }
    }
}

// ---------------------------------------------------------------------------
// Launch: inputs per metadata order: x, central_species, W1, b1, W2, b2
// ---------------------------------------------------------------------------
extern "C" void kernel_launch(void* const* d_in, const int* in_sizes, int n_in,
                              void* d_out, int out_size)
{
    const float* x   = (const float*)d_in[0];
    const int*   spw = (const int*)d_in[1];     // int32 words of species buffer
    const float* W1  = (const float*)d_in[2];
    const float* b1  = (const float*)d_in[3];
    const float* W2  = (const float*)d_in[4];
    const float* b2  = (const float*)d_in[5];
    float*       out = (float*)d_out;

    float* Hptr;
    cudaGetSymbolAddress((void**)&Hptr, g_H);

    k_reset<<<1, 32>>>();
    k_probe<<<32768 / 256, 256>>>(spw);
    k_scatter<<<N_TOK / 256, 256>>>(spw);

    // Pass A: H = silu(x @ W1[s] + b1[s]);  grid covers worst-case bucket size.
    dim3 gA(N_TOK / 128, D_HID / 128, NSPEC);
    mlp_gemm<D_IN, D_HID, true><<<gA, 256>>>(x, W1, b1, Hptr);

    // Pass B: out = H @ W2[s] + b2[s]
    dim3 gB(N_TOK / 128, D_OUT / 128, NSPEC);
    mlp_gemm<D_HID, D_OUT, false><<<gB, 256>>>(Hptr, W2, b2, out);
}

// round 4
// speedup vs baseline: 2.7086x; 2.7086x over previous
#include <cuda_runtime.h>
#include <cuda_bf16.h>
#include <stdint.h>
#include <math.h>

#define NT    65536
#define NSPEC 4
#define DIN   256
#define DHID  1024
#define DOUT  256

// ---------------------------------------------------------------------------
// Device-global scratch (allocation-free rule).
// ---------------------------------------------------------------------------
__device__ int g_cnt[NSPEC];
__device__ int g_off[NSPEC];
__device__ int g_or_odd;
__device__ int g_idx[NSPEC * NT];
__device__ __nv_bfloat16 g_xh[(size_t)NT * DIN];
__device__ __nv_bfloat16 g_xl[(size_t)NT * DIN];
__device__ __nv_bfloat16 g_Hh[(size_t)NT * DHID];
__device__ __nv_bfloat16 g_Hl[(size_t)NT * DHID];
__device__ __nv_bfloat16 g_w1h[(size_t)NSPEC * DHID * DIN];   // [s][n][k]
__device__ __nv_bfloat16 g_w1l[(size_t)NSPEC * DHID * DIN];
__device__ __nv_bfloat16 g_w2h[(size_t)NSPEC * DOUT * DHID];
__device__ __nv_bfloat16 g_w2l[(size_t)NSPEC * DOUT * DHID];

// ---------------------------------------------------------------------------
// Helpers
// ---------------------------------------------------------------------------
__device__ __forceinline__ uint32_t s2u(const void* p) {
    uint32_t a;
    asm("{ .reg .u64 t; cvta.to.shared.u64 t, %1; cvt.u32.u64 %0, t; }" : "=r"(a) : "l"(p));
    return a;
}
__device__ __forceinline__ uint32_t swz(uint32_t o) { return o ^ ((o >> 3) & 0x70u); }

#define CP_COMMIT() asm volatile("cp.async.commit_group;" ::: "memory")
template<int N> __device__ __forceinline__ void cp_wait() {
    asm volatile("cp.async.wait_group %0;" :: "n"(N) : "memory");
}
// cp.async with runtime src-size (0 => zero-fill, no read)
__device__ __forceinline__ void cp16z(uint32_t dst, const void* src, unsigned sz) {
    asm volatile("cp.async.cg.shared.global [%0], [%1], 16, %2;"
                 :: "r"(dst), "l"(src), "r"(sz) : "memory");
}

#define LDM4(r, a) \
    asm volatile("ldmatrix.sync.aligned.m8n8.x4.shared.b16 {%0,%1,%2,%3}, [%4];" \
                 : "=r"((r)[0]), "=r"((r)[1]), "=r"((r)[2]), "=r"((r)[3]) : "r"(a))

#define MMA(c, a, b) \
    asm volatile("mma.sync.aligned.m16n8k16.row.col.f32.bf16.bf16.f32 " \
                 "{%0,%1,%2,%3},{%4,%5,%6,%7},{%8,%9},{%0,%1,%2,%3};" \
                 : "+f"((c)[0]), "+f"((c)[1]), "+f"((c)[2]), "+f"((c)[3]) \
                 : "r"((a)[0]), "r"((a)[1]), "r"((a)[2]), "r"((a)[3]), \
                   "r"((b)[0]), "r"((b)[1]))

// ---------------------------------------------------------------------------
// Routing (species dtype probe: JAX x64-off silently emits int32)
// ---------------------------------------------------------------------------
__global__ void k_reset() {
    if (threadIdx.x < NSPEC) g_cnt[threadIdx.x] = 0;
    if (threadIdx.x == 0)    g_or_odd = 0;
}
__global__ void k_probe(const int* __restrict__ w) {
    int i = blockIdx.x * blockDim.x + threadIdx.x;   // odd-word index 0..32767
    int v = w[2 * i + 1];
    for (int o = 16; o > 0; o >>= 1) v |= __shfl_xor_sync(0xffffffffu, v, o);
    if ((threadIdx.x & 31) == 0 && v) atomicOr(&g_or_odd, 1);
}
__global__ void k_scatter(const int* __restrict__ w) {
    int i = blockIdx.x * blockDim.x + threadIdx.x;
    if (i >= NT) return;
    bool is64 = (g_or_odd == 0);
    int s = is64 ? w[2 * i] : w[i];
    if ((unsigned)s < NSPEC) {
        int p = atomicAdd(&g_cnt[s], 1);
        g_idx[s * NT + p] = i;
    }
}
__global__ void k_prefix() {
    if (threadIdx.x == 0) {
        int a = 0;
        for (int s = 0; s < NSPEC; s++) { g_off[s] = a; a += g_cnt[s]; }
    }
}

// ---------------------------------------------------------------------------
// Conversions: x -> bf16 hi/lo; W[s][k][n] -> Wt[s][n][k] bf16 hi/lo
// ---------------------------------------------------------------------------
__global__ void conv_x(const float* __restrict__ x) {
    size_t i = ((size_t)blockIdx.x * 256 + threadIdx.x) * 4;
    float4 v = *(const float4*)(x + i);
    __nv_bfloat16 h0 = __float2bfloat16(v.x), h1 = __float2bfloat16(v.y);
    __nv_bfloat16 h2 = __float2bfloat16(v.z), h3 = __float2bfloat16(v.w);
    __nv_bfloat16 l0 = __float2bfloat16(v.x - __bfloat162float(h0));
    __nv_bfloat16 l1 = __float2bfloat16(v.y - __bfloat162float(h1));
    __nv_bfloat16 l2 = __float2bfloat16(v.z - __bfloat162float(h2));
    __nv_bfloat16 l3 = __float2bfloat16(v.w - __bfloat162float(h3));
    uint2 ph, pl;
    ph.x = (uint32_t)__bfloat16_as_ushort(h0) | ((uint32_t)__bfloat16_as_ushort(h1) << 16);
    ph.y = (uint32_t)__bfloat16_as_ushort(h2) | ((uint32_t)__bfloat16_as_ushort(h3) << 16);
    pl.x = (uint32_t)__bfloat16_as_ushort(l0) | ((uint32_t)__bfloat16_as_ushort(l1) << 16);
    pl.y = (uint32_t)__bfloat16_as_ushort(l2) | ((uint32_t)__bfloat16_as_ushort(l3) << 16);
    ((uint2*)g_xh)[i / 4] = ph;
    ((uint2*)g_xl)[i / 4] = pl;
}

template<int KD, int ND>
__global__ void conv_w(const float* __restrict__ W,
                       __nv_bfloat16* __restrict__ Th,
                       __nv_bfloat16* __restrict__ Tl) {
    __shared__ float sm[32][33];
    int s = blockIdx.z, k0 = blockIdx.x * 32, n0 = blockIdx.y * 32;
    int tx = threadIdx.x, ty = threadIdx.y;   // (32, 8)
    const float* Wp = W + (size_t)s * KD * ND;
#pragma unroll
    for (int j = 0; j < 4; j++)
        sm[ty + j * 8][tx] = Wp[(size_t)(k0 + ty + j * 8) * ND + n0 + tx];
    __syncthreads();
#pragma unroll
    for (int j = 0; j < 4; j++) {
        int n = ty + j * 8;
        float v = sm[tx][n];
        __nv_bfloat16 h = __float2bfloat16(v);
        __nv_bfloat16 l = __float2bfloat16(v - __bfloat162float(h));
        size_t o = ((size_t)s * ND + n0 + n) * KD + k0 + tx;
        Th[o] = h; Tl[o] = l;
    }
}

// ---------------------------------------------------------------------------
// mma.sync split-bf16 GEMM over one species bucket.
//   Block tile 128(M) x 128(N), K chunks of 64. 8 warps: warp tile 64x32.
//   C = Ah*Bh + Ah*Bl + Al*Bh (fp32 accum) -- ~fp32 accuracy.
// Dynamic SMEM: 2 buffers x 64KB; each: Ah 16K | Al 16K | Bh 16K | Bl 16K,
//   rows of 64 bf16 (128B) with SW128 swizzle.
// ---------------------------------------------------------------------------
#define GEMM_SMEM 131072

template<int KT, int NDIM, bool GATHER_A, bool SCATTER_OUT, bool DO_SILU>
__global__ void __launch_bounds__(256, 1)
moe_gemm(const __nv_bfloat16* __restrict__ Ah, const __nv_bfloat16* __restrict__ Al,
         const __nv_bfloat16* __restrict__ Bh, const __nv_bfloat16* __restrict__ Bl,
         const float* __restrict__ bias,
         __nv_bfloat16* __restrict__ Oh, __nv_bfloat16* __restrict__ Ol,
         float* __restrict__ Of)
{
    constexpr int NC = KT / 64;
    extern __shared__ char dyn[];
    __shared__ int   tok[128];
    __shared__ float bsm[128];

    const int tid = threadIdx.x, wid = tid >> 5, lane = tid & 31;
    const int s   = blockIdx.z;
    const int cnt = g_cnt[s];
    const int m0  = blockIdx.x * 128;
    if (m0 >= cnt) return;
    const int n0    = blockIdx.y * 128;
    const int valid = min(128, cnt - m0);
    const int off   = g_off[s];
    const uint32_t sbase = s2u(dyn);

    for (int i = tid; i < 128; i += 256)
        tok[i] = (i < valid) ? g_idx[s * NT + m0 + i] : -1;
    if (tid < 128) bsm[tid] = bias[(size_t)s * NDIM + n0 + tid];
    __syncthreads();

    auto issue = [&](int c) {
        const int k0 = c * 64;
        const uint32_t bb = sbase + (uint32_t)(c & 1) * 65536u;
#pragma unroll
        for (int i = 0; i < 8; i++) {          // A: hi/lo x 128 rows x 8 units
            int t = tid + i * 256;
            int arr = t >> 10, row = (t >> 3) & 127, u = t & 7;
            int gr;
            if (GATHER_A) gr = tok[row];
            else          gr = (row < valid) ? (off + m0 + row) : -1;
            const __nv_bfloat16* src =
                (arr ? Al : Ah) + (size_t)max(gr, 0) * KT + k0 + u * 8;
            uint32_t dst = bb + (uint32_t)arr * 16384u + swz((uint32_t)row * 128u + u * 16u);
            cp16z(dst, src, (gr >= 0) ? 16u : 0u);
        }
#pragma unroll
        for (int i = 0; i < 8; i++) {          // B: hi/lo x 128 rows x 8 units
            int t = tid + i * 256;
            int arr = t >> 10, row = (t >> 3) & 127, u = t & 7;
            const __nv_bfloat16* src =
                (arr ? Bl : Bh) + ((size_t)s * NDIM + n0 + row) * KT + k0 + u * 8;
            uint32_t dst = bb + 32768u + (uint32_t)arr * 16384u
                         + swz((uint32_t)row * 128u + u * 16u);
            cp16z(dst, src, 16u);
        }
        CP_COMMIT();
    };

    float acc[4][4][4];
#pragma unroll
    for (int a = 0; a < 4; a++)
#pragma unroll
        for (int b = 0; b < 4; b++)
#pragma unroll
            for (int q = 0; q < 4; q++) acc[a][b][q] = 0.f;

    const int wm = wid & 1;            // M warp (0-1): 64 rows each
    const int wn = wid >> 1;           // N warp (0-3): 32 cols each
    const int ra = (lane & 7) + ((lane >> 3) & 1) * 8;   // A ldmatrix row
    const int ca = ((lane >> 4) & 1) * 8;                // A ldmatrix col (bf16)
    const int rb = (lane & 7) + ((lane >> 4) & 1) * 8;   // B ldmatrix row (n)
    const int cb = ((lane >> 3) & 1) * 8;                // B ldmatrix col (k)

    issue(0);
#pragma unroll 1
    for (int c = 0; c < NC; c++) {
        if (c + 1 < NC) { issue(c + 1); cp_wait<1>(); }
        else            { cp_wait<0>(); }
        __syncthreads();
        const uint32_t bb = sbase + (uint32_t)(c & 1) * 65536u;
#pragma unroll
        for (int ks = 0; ks < 4; ks++) {
            uint32_t af[4][4], alf[4][4], bf[2][4], blf[2][4];
#pragma unroll
            for (int mt = 0; mt < 4; mt++) {
                uint32_t o = (uint32_t)((wm * 64 + mt * 16 + ra) * 128
                                        + (ks * 16 + ca) * 2);
                uint32_t ad = bb + swz(o);
                LDM4(af[mt], ad);
                LDM4(alf[mt], ad + 16384u);
            }
#pragma unroll
            for (int np = 0; np < 2; np++) {
                uint32_t o = (uint32_t)((wn * 32 + np * 16 + rb) * 128
                                        + (ks * 16 + cb) * 2);
                uint32_t ad = bb + 32768u + swz(o);
                LDM4(bf[np], ad);
                LDM4(blf[np], ad + 16384u);
            }
#pragma unroll
            for (int mt = 0; mt < 4; mt++)
#pragma unroll
                for (int nt = 0; nt < 4; nt++) {
                    uint32_t* bh2 = &bf[nt >> 1][(nt & 1) * 2];
                    uint32_t* bl2 = &blf[nt >> 1][(nt & 1) * 2];
                    MMA(acc[mt][nt], af[mt], bh2);
                    MMA(acc[mt][nt], af[mt], bl2);
                    MMA(acc[mt][nt], alf[mt], bh2);
                }
        }
        __syncthreads();
    }

    // Epilogue: bias (+SiLU+split) and store. Acc row = wm*64+mt*16+gid(+8),
    // col = wn*32+nt*8+tig*2.
    const int gid = lane >> 2, tig = lane & 3;
#pragma unroll
    for (int mt = 0; mt < 4; mt++)
#pragma unroll
        for (int half = 0; half < 2; half++) {
            int lrow = wm * 64 + mt * 16 + gid + half * 8;
            if (lrow >= valid) continue;
            int orow = SCATTER_OUT ? tok[lrow] : (off + m0 + lrow);
#pragma unroll
            for (int nt = 0; nt < 4; nt++) {
                int col = wn * 32 + nt * 8 + tig * 2;
                float v0 = acc[mt][nt][half * 2 + 0] + bsm[col];
                float v1 = acc[mt][nt][half * 2 + 1] + bsm[col + 1];
                if (DO_SILU) {
                    v0 = v0 / (1.f + __expf(-v0));
                    v1 = v1 / (1.f + __expf(-v1));
                    __nv_bfloat16 h0 = __float2bfloat16(v0);
                    __nv_bfloat16 h1 = __float2bfloat16(v1);
                    __nv_bfloat16 l0 = __float2bfloat16(v0 - __bfloat162float(h0));
                    __nv_bfloat16 l1 = __float2bfloat16(v1 - __bfloat162float(h1));
                    uint32_t ph = (uint32_t)__bfloat16_as_ushort(h0)
                                | ((uint32_t)__bfloat16_as_ushort(h1) << 16);
                    uint32_t pl = (uint32_t)__bfloat16_as_ushort(l0)
                                | ((uint32_t)__bfloat16_as_ushort(l1) << 16);
                    *(uint32_t*)(Oh + (size_t)orow * NDIM + n0 + col) = ph;
                    *(uint32_t*)(Ol + (size_t)orow * NDIM + n0 + col) = pl;
                } else {
                    float2 v = make_float2(v0, v1);
                    *(float2*)(Of + (size_t)orow * NDIM + n0 + col) = v;
                }
            }
        }
}

// ---------------------------------------------------------------------------
// Launch: inputs: x, central_species, W1, b1, W2, b2
// ---------------------------------------------------------------------------
extern "C" void kernel_launch(void* const* d_in, const int* in_sizes, int n_in,
                              void* d_out, int out_size)
{
    const float* x   = (const float*)d_in[0];
    const int*   spw = (const int*)d_in[1];
    const float* W1  = (const float*)d_in[2];
    const float* b1  = (const float*)d_in[3];
    const float* W2  = (const float*)d_in[4];
    const float* b2  = (const float*)d_in[5];
    float*       out = (float*)d_out;

    __nv_bfloat16 *xh, *xl, *Hh, *Hl, *w1h, *w1l, *w2h, *w2l;
    cudaGetSymbolAddress((void**)&xh,  g_xh);
    cudaGetSymbolAddress((void**)&xl,  g_xl);
    cudaGetSymbolAddress((void**)&Hh,  g_Hh);
    cudaGetSymbolAddress((void**)&Hl,  g_Hl);
    cudaGetSymbolAddress((void**)&w1h, g_w1h);
    cudaGetSymbolAddress((void**)&w1l, g_w1l);
    cudaGetSymbolAddress((void**)&w2h, g_w2h);
    cudaGetSymbolAddress((void**)&w2l, g_w2l);

    cudaFuncSetAttribute(moe_gemm<DIN,  DHID, true,  false, true>,
                         cudaFuncAttributeMaxDynamicSharedMemorySize, GEMM_SMEM);
    cudaFuncSetAttribute(moe_gemm<DHID, DOUT, false, true,  false>,
                         cudaFuncAttributeMaxDynamicSharedMemorySize, GEMM_SMEM);

    k_reset  <<<1, 32>>>();
    k_probe  <<<128, 256>>>(spw);
    k_scatter<<<NT / 256, 256>>>(spw);
    k_prefix <<<1, 1>>>();

    conv_x<<<NT * DIN / 4 / 256, 256>>>(x);
    conv_w<DIN,  DHID><<<dim3(DIN / 32,  DHID / 32, NSPEC), dim3(32, 8)>>>(W1, w1h, w1l);
    conv_w<DHID, DOUT><<<dim3(DHID / 32, DOUT / 32, NSPEC), dim3(32, 8)>>>(W2, w2h, w2l);

    // GEMM1: H = silu(x @ W1[s] + b1[s]) -> compact bf16 hi/lo
    moe_gemm<DIN, DHID, true, false, true>
        <<<dim3(NT / 128, DHID / 128, NSPEC), 256, GEMM_SMEM>>>(
            xh, xl, w1h, w1l, b1, Hh, Hl, nullptr);

    // GEMM2: out = H @ W2[s] + b2[s] -> scatter fp32 by token
    moe_gemm<DHID, DOUT, false, true, false>
        <<<dim3(NT / 128, DOUT / 128, NSPEC), 256, GEMM_SMEM>>>(
            Hh, Hl, w2h, w2l, b2, nullptr, nullptr, out);
}

// round 5
// speedup vs baseline: 2.7151x; 1.0024x over previous
#include <cuda_runtime.h>
#include <cuda_bf16.h>
#include <stdint.h>
#include <math.h>

#define NT    65536
#define NSPEC 4
#define DIN   256
#define DHID  1024
#define DOUT  256

// ---------------------------------------------------------------------------
// Device-global scratch (allocation-free rule).
// ---------------------------------------------------------------------------
__device__ int g_cnt[NSPEC];
__device__ int g_off[NSPEC];
__device__ int g_or_odd;
__device__ int g_idx[NSPEC * NT];
__device__ __nv_bfloat16 g_xh[(size_t)NT * DIN];
__device__ __nv_bfloat16 g_xl[(size_t)NT * DIN];
__device__ __nv_bfloat16 g_Hh[(size_t)NT * DHID];
__device__ __nv_bfloat16 g_Hl[(size_t)NT * DHID];
__device__ __nv_bfloat16 g_w1h[(size_t)NSPEC * DHID * DIN];   // [s][n][k]
__device__ __nv_bfloat16 g_w1l[(size_t)NSPEC * DHID * DIN];
__device__ __nv_bfloat16 g_w2h[(size_t)NSPEC * DOUT * DHID];
__device__ __nv_bfloat16 g_w2l[(size_t)NSPEC * DOUT * DHID];

// ---------------------------------------------------------------------------
// Helpers
// ---------------------------------------------------------------------------
__device__ __forceinline__ uint32_t s2u(const void* p) {
    uint32_t a;
    asm("{ .reg .u64 t; cvta.to.shared.u64 t, %1; cvt.u32.u64 %0, t; }" : "=r"(a) : "l"(p));
    return a;
}
__device__ __forceinline__ uint32_t swz(uint32_t o) { return o ^ ((o >> 3) & 0x70u); }

#define CP_COMMIT() asm volatile("cp.async.commit_group;" ::: "memory")
template<int N> __device__ __forceinline__ void cp_wait() {
    asm volatile("cp.async.wait_group %0;" :: "n"(N) : "memory");
}
// cp.async with runtime src-size (0 => zero-fill, no read)
__device__ __forceinline__ void cp16z(uint32_t dst, const void* src, unsigned sz) {
    asm volatile("cp.async.cg.shared.global [%0], [%1], 16, %2;"
                 :: "r"(dst), "l"(src), "r"(sz) : "memory");
}

#define LDM4(r, a) \
    asm volatile("ldmatrix.sync.aligned.m8n8.x4.shared.b16 {%0,%1,%2,%3}, [%4];" \
                 : "=r"((r)[0]), "=r"((r)[1]), "=r"((r)[2]), "=r"((r)[3]) : "r"(a))

#define MMA(c, a, b) \
    asm volatile("mma.sync.aligned.m16n8k16.row.col.f32.bf16.bf16.f32 " \
                 "{%0,%1,%2,%3},{%4,%5,%6,%7},{%8,%9},{%0,%1,%2,%3};" \
                 : "+f"((c)[0]), "+f"((c)[1]), "+f"((c)[2]), "+f"((c)[3]) \
                 : "r"((a)[0]), "r"((a)[1]), "r"((a)[2]), "r"((a)[3]), \
                   "r"((b)[0]), "r"((b)[1]))

// ---------------------------------------------------------------------------
// Routing (species dtype probe: JAX x64-off silently emits int32)
// ---------------------------------------------------------------------------
__global__ void k_reset() {
    if (threadIdx.x < NSPEC) g_cnt[threadIdx.x] = 0;
    if (threadIdx.x == 0)    g_or_odd = 0;
}
__global__ void k_probe(const int* __restrict__ w) {
    int i = blockIdx.x * blockDim.x + threadIdx.x;   // odd-word index 0..32767
    int v = w[2 * i + 1];
    for (int o = 16; o > 0; o >>= 1) v |= __shfl_xor_sync(0xffffffffu, v, o);
    if ((threadIdx.x & 31) == 0 && v) atomicOr(&g_or_odd, 1);
}
__global__ void k_scatter(const int* __restrict__ w) {
    int i = blockIdx.x * blockDim.x + threadIdx.x;
    if (i >= NT) return;
    bool is64 = (g_or_odd == 0);
    int s = is64 ? w[2 * i] : w[i];
    if ((unsigned)s < NSPEC) {
        int p = atomicAdd(&g_cnt[s], 1);
        g_idx[s * NT + p] = i;
    }
}
__global__ void k_prefix() {
    if (threadIdx.x == 0) {
        int a = 0;
        for (int s = 0; s < NSPEC; s++) { g_off[s] = a; a += g_cnt[s]; }
    }
}

// ---------------------------------------------------------------------------
// Conversions: x -> bf16 hi/lo; W[s][k][n] -> Wt[s][n][k] bf16 hi/lo
// ---------------------------------------------------------------------------
__global__ void conv_x(const float* __restrict__ x) {
    size_t i = ((size_t)blockIdx.x * 256 + threadIdx.x) * 4;
    float4 v = *(const float4*)(x + i);
    __nv_bfloat16 h0 = __float2bfloat16(v.x), h1 = __float2bfloat16(v.y);
    __nv_bfloat16 h2 = __float2bfloat16(v.z), h3 = __float2bfloat16(v.w);
    __nv_bfloat16 l0 = __float2bfloat16(v.x - __bfloat162float(h0));
    __nv_bfloat16 l1 = __float2bfloat16(v.y - __bfloat162float(h1));
    __nv_bfloat16 l2 = __float2bfloat16(v.z - __bfloat162float(h2));
    __nv_bfloat16 l3 = __float2bfloat16(v.w - __bfloat162float(h3));
    uint2 ph, pl;
    ph.x = (uint32_t)__bfloat16_as_ushort(h0) | ((uint32_t)__bfloat16_as_ushort(h1) << 16);
    ph.y = (uint32_t)__bfloat16_as_ushort(h2) | ((uint32_t)__bfloat16_as_ushort(h3) << 16);
    pl.x = (uint32_t)__bfloat16_as_ushort(l0) | ((uint32_t)__bfloat16_as_ushort(l1) << 16);
    pl.y = (uint32_t)__bfloat16_as_ushort(l2) | ((uint32_t)__bfloat16_as_ushort(l3) << 16);
    ((uint2*)g_xh)[i / 4] = ph;
    ((uint2*)g_xl)[i / 4] = pl;
}

template<int KD, int ND>
__global__ void conv_w(const float* __restrict__ W,
                       __nv_bfloat16* __restrict__ Th,
                       __nv_bfloat16* __restrict__ Tl) {
    __shared__ float sm[32][33];
    int s = blockIdx.z, k0 = blockIdx.x * 32, n0 = blockIdx.y * 32;
    int tx = threadIdx.x, ty = threadIdx.y;   // (32, 8)
    const float* Wp = W + (size_t)s * KD * ND;
#pragma unroll
    for (int j = 0; j < 4; j++)
        sm[ty + j * 8][tx] = Wp[(size_t)(k0 + ty + j * 8) * ND + n0 + tx];
    __syncthreads();
#pragma unroll
    for (int j = 0; j < 4; j++) {
        int n = ty + j * 8;
        float v = sm[tx][n];
        __nv_bfloat16 h = __float2bfloat16(v);
        __nv_bfloat16 l = __float2bfloat16(v - __bfloat162float(h));
        size_t o = ((size_t)s * ND + n0 + n) * KD + k0 + tx;
        Th[o] = h; Tl[o] = l;
    }
}

// ---------------------------------------------------------------------------
// mma.sync split-bf16 GEMM over one species bucket.
//   Block tile 128(M) x 128(N), K chunks of 64. 8 warps: warp tile 64x32.
//   C = Ah*Bh + Ah*Bl + Al*Bh (fp32 accum) -- ~fp32 accuracy.
// Dynamic SMEM: 2 buffers x 64KB; each: Ah 16K | Al 16K | Bh 16K | Bl 16K,
//   rows of 64 bf16 (128B) with SW128 swizzle.
// ---------------------------------------------------------------------------
#define GEMM_SMEM 131072

template<int KT, int NDIM, bool GATHER_A, bool SCATTER_OUT, bool DO_SILU>
__global__ void __launch_bounds__(256, 1)
moe_gemm(const __nv_bfloat16* __restrict__ Ah, const __nv_bfloat16* __restrict__ Al,
         const __nv_bfloat16* __restrict__ Bh, const __nv_bfloat16* __restrict__ Bl,
         const float* __restrict__ bias,
         __nv_bfloat16* __restrict__ Oh, __nv_bfloat16* __restrict__ Ol,
         float* __restrict__ Of)
{
    constexpr int NC = KT / 64;
    extern __shared__ char dyn[];
    __shared__ int   tok[128];
    __shared__ float bsm[128];

    const int tid = threadIdx.x, wid = tid >> 5, lane = tid & 31;
    const int s   = blockIdx.z;
    const int cnt = g_cnt[s];
    const int m0  = blockIdx.x * 128;
    if (m0 >= cnt) return;
    const int n0    = blockIdx.y * 128;
    const int valid = min(128, cnt - m0);
    const int off   = g_off[s];
    const uint32_t sbase = s2u(dyn);

    for (int i = tid; i < 128; i += 256)
        tok[i] = (i < valid) ? g_idx[s * NT + m0 + i] : -1;
    if (tid < 128) bsm[tid] = bias[(size_t)s * NDIM + n0 + tid];
    __syncthreads();

    auto issue = [&](int c) {
        const int k0 = c * 64;
        const uint32_t bb = sbase + (uint32_t)(c & 1) * 65536u;
#pragma unroll
        for (int i = 0; i < 8; i++) {          // A: hi/lo x 128 rows x 8 units
            int t = tid + i * 256;
            int arr = t >> 10, row = (t >> 3) & 127, u = t & 7;
            int gr;
            if (GATHER_A) gr = tok[row];
            else          gr = (row < valid) ? (off + m0 + row) : -1;
            const __nv_bfloat16* src =
                (arr ? Al : Ah) + (size_t)max(gr, 0) * KT + k0 + u * 8;
            uint32_t dst = bb + (uint32_t)arr * 16384u + swz((uint32_t)row * 128u + u * 16u);
            cp16z(dst, src, (gr >= 0) ? 16u : 0u);
        }
#pragma unroll
        for (int i = 0; i < 8; i++) {          // B: hi/lo x 128 rows x 8 units
            int t = tid + i * 256;
            int arr = t >> 10, row = (t >> 3) & 127, u = t & 7;
            const __nv_bfloat16* src =
                (arr ? Bl : Bh) + ((size_t)s * NDIM + n0 + row) * KT + k0 + u * 8;
            uint32_t dst = bb + 32768u + (uint32_t)arr * 16384u
                         + swz((uint32_t)row * 128u + u * 16u);
            cp16z(dst, src, 16u);
        }
        CP_COMMIT();
    };

    float acc[4][4][4];
#pragma unroll
    for (int a = 0; a < 4; a++)
#pragma unroll
        for (int b = 0; b < 4; b++)
#pragma unroll
            for (int q = 0; q < 4; q++) acc[a][b][q] = 0.f;

    const int wm = wid & 1;            // M warp (0-1): 64 rows each
    const int wn = wid >> 1;           // N warp (0-3): 32 cols each
    const int ra = (lane & 7) + ((lane >> 3) & 1) * 8;   // A ldmatrix row
    const int ca = ((lane >> 4) & 1) * 8;                // A ldmatrix col (bf16)
    const int rb = (lane & 7) + ((lane >> 4) & 1) * 8;   // B ldmatrix row (n)
    const int cb = ((lane >> 3) & 1) * 8;                // B ldmatrix col (k)

    issue(0);
#pragma unroll 1
    for (int c = 0; c < NC; c++) {
        if (c + 1 < NC) { issue(c + 1); cp_wait<1>(); }
        else            { cp_wait<0>(); }
        __syncthreads();
        const uint32_t bb = sbase + (uint32_t)(c & 1) * 65536u;
#pragma unroll
        for (int ks = 0; ks < 4; ks++) {
            uint32_t af[4][4], alf[4][4], bf[2][4], blf[2][4];
#pragma unroll
            for (int mt = 0; mt < 4; mt++) {
                uint32_t o = (uint32_t)((wm * 64 + mt * 16 + ra) * 128
                                        + (ks * 16 + ca) * 2);
                uint32_t ad = bb + swz(o);
                LDM4(af[mt], ad);
                LDM4(alf[mt], ad + 16384u);
            }
#pragma unroll
            for (int np = 0; np < 2; np++) {
                uint32_t o = (uint32_t)((wn * 32 + np * 16 + rb) * 128
                                        + (ks * 16 + cb) * 2);
                uint32_t ad = bb + 32768u + swz(o);
                LDM4(bf[np], ad);
                LDM4(blf[np], ad + 16384u);
            }
#pragma unroll
            for (int mt = 0; mt < 4; mt++)
#pragma unroll
                for (int nt = 0; nt < 4; nt++) {
                    uint32_t* bh2 = &bf[nt >> 1][(nt & 1) * 2];
                    uint32_t* bl2 = &blf[nt >> 1][(nt & 1) * 2];
                    MMA(acc[mt][nt], af[mt], bh2);
                    MMA(acc[mt][nt], af[mt], bl2);
                    MMA(acc[mt][nt], alf[mt], bh2);
                }
        }
        __syncthreads();
    }

    // Epilogue: bias (+SiLU+split) and store. Acc row = wm*64+mt*16+gid(+8),
    // col = wn*32+nt*8+tig*2.
    const int gid = lane >> 2, tig = lane & 3;
#pragma unroll
    for (int mt = 0; mt < 4; mt++)
#pragma unroll
        for (int half = 0; half < 2; half++) {
            int lrow = wm * 64 + mt * 16 + gid + half * 8;
            if (lrow >= valid) continue;
            int orow = SCATTER_OUT ? tok[lrow] : (off + m0 + lrow);
#pragma unroll
            for (int nt = 0; nt < 4; nt++) {
                int col = wn * 32 + nt * 8 + tig * 2;
                float v0 = acc[mt][nt][half * 2 + 0] + bsm[col];
                float v1 = acc[mt][nt][half * 2 + 1] + bsm[col + 1];
                if (DO_SILU) {
                    v0 = v0 / (1.f + __expf(-v0));
                    v1 = v1 / (1.f + __expf(-v1));
                    __nv_bfloat16 h0 = __float2bfloat16(v0);
                    __nv_bfloat16 h1 = __float2bfloat16(v1);
                    __nv_bfloat16 l0 = __float2bfloat16(v0 - __bfloat162float(h0));
                    __nv_bfloat16 l1 = __float2bfloat16(v1 - __bfloat162float(h1));
                    uint32_t ph = (uint32_t)__bfloat16_as_ushort(h0)
                                | ((uint32_t)__bfloat16_as_ushort(h1) << 16);
                    uint32_t pl = (uint32_t)__bfloat16_as_ushort(l0)
                                | ((uint32_t)__bfloat16_as_ushort(l1) << 16);
                    *(uint32_t*)(Oh + (size_t)orow * NDIM + n0 + col) = ph;
                    *(uint32_t*)(Ol + (size_t)orow * NDIM + n0 + col) = pl;
                } else {
                    float2 v = make_float2(v0, v1);
                    *(float2*)(Of + (size_t)orow * NDIM + n0 + col) = v;
                }
            }
        }
}

// ---------------------------------------------------------------------------
// Launch: inputs: x, central_species, W1, b1, W2, b2
// ---------------------------------------------------------------------------
extern "C" void kernel_launch(void* const* d_in, const int* in_sizes, int n_in,
                              void* d_out, int out_size)
{
    const float* x   = (const float*)d_in[0];
    const int*   spw = (const int*)d_in[1];
    const float* W1  = (const float*)d_in[2];
    const float* b1  = (const float*)d_in[3];
    const float* W2  = (const float*)d_in[4];
    const float* b2  = (const float*)d_in[5];
    float*       out = (float*)d_out;

    __nv_bfloat16 *xh, *xl, *Hh, *Hl, *w1h, *w1l, *w2h, *w2l;
    cudaGetSymbolAddress((void**)&xh,  g_xh);
    cudaGetSymbolAddress((void**)&xl,  g_xl);
    cudaGetSymbolAddress((void**)&Hh,  g_Hh);
    cudaGetSymbolAddress((void**)&Hl,  g_Hl);
    cudaGetSymbolAddress((void**)&w1h, g_w1h);
    cudaGetSymbolAddress((void**)&w1l, g_w1l);
    cudaGetSymbolAddress((void**)&w2h, g_w2h);
    cudaGetSymbolAddress((void**)&w2l, g_w2l);

    cudaFuncSetAttribute(moe_gemm<DIN,  DHID, true,  false, true>,
                         cudaFuncAttributeMaxDynamicSharedMemorySize, GEMM_SMEM);
    cudaFuncSetAttribute(moe_gemm<DHID, DOUT, false, true,  false>,
                         cudaFuncAttributeMaxDynamicSharedMemorySize, GEMM_SMEM);

    k_reset  <<<1, 32>>>();
    k_probe  <<<128, 256>>>(spw);
    k_scatter<<<NT / 256, 256>>>(spw);
    k_prefix <<<1, 1>>>();

    conv_x<<<NT * DIN / 4 / 256, 256>>>(x);
    conv_w<DIN,  DHID><<<dim3(DIN / 32,  DHID / 32, NSPEC), dim3(32, 8)>>>(W1, w1h, w1l);
    conv_w<DHID, DOUT><<<dim3(DHID / 32, DOUT / 32, NSPEC), dim3(32, 8)>>>(W2, w2h, w2l);

    // GEMM1: H = silu(x @ W1[s] + b1[s]) -> compact bf16 hi/lo
    moe_gemm<DIN, DHID, true, false, true>
        <<<dim3(NT / 128, DHID / 128, NSPEC), 256, GEMM_SMEM>>>(
            xh, xl, w1h, w1l, b1, Hh, Hl, nullptr);

    // GEMM2: out = H @ W2[s] + b2[s] -> scatter fp32 by token
    moe_gemm<DHID, DOUT, false, true, false>
        <<<dim3(NT / 128, DOUT / 128, NSPEC), 256, GEMM_SMEM>>>(
            Hh, Hl, w2h, w2l, b2, nullptr, nullptr, out);
}

// round 6
// speedup vs baseline: 2.7775x; 1.0230x over previous
#include <cuda_runtime.h>
#include <cuda_bf16.h>
#include <stdint.h>
#include <math.h>

#define NT    65536
#define NSPEC 4
#define DIN   256
#define DHID  1024
#define DOUT  256

// ---------------------------------------------------------------------------
// Device-global scratch (allocation-free rule).
// ---------------------------------------------------------------------------
__device__ int g_cnt[NSPEC];
__device__ int g_off[NSPEC];
__device__ int g_or_odd;
__device__ int g_idx[NSPEC * NT];
__device__ __nv_bfloat16 g_xh[(size_t)NT * DIN];
__device__ __nv_bfloat16 g_xl[(size_t)NT * DIN];
__device__ __nv_bfloat16 g_Hh[(size_t)NT * DHID];
__device__ __nv_bfloat16 g_Hl[(size_t)NT * DHID];
__device__ __nv_bfloat16 g_w1h[(size_t)NSPEC * DHID * DIN];   // [s][n][k]
__device__ __nv_bfloat16 g_w1l[(size_t)NSPEC * DHID * DIN];
__device__ __nv_bfloat16 g_w2h[(size_t)NSPEC * DOUT * DHID];
__device__ __nv_bfloat16 g_w2l[(size_t)NSPEC * DOUT * DHID];

// ---------------------------------------------------------------------------
// Helpers
// ---------------------------------------------------------------------------
__device__ __forceinline__ uint32_t s2u(const void* p) {
    uint32_t a;
    asm("{ .reg .u64 t; cvta.to.shared.u64 t, %1; cvt.u32.u64 %0, t; }" : "=r"(a) : "l"(p));
    return a;
}
__device__ __forceinline__ uint32_t swz(uint32_t o) { return o ^ ((o >> 3) & 0x70u); }

#define CP_COMMIT() asm volatile("cp.async.commit_group;" ::: "memory")
template<int N> __device__ __forceinline__ void cp_wait() {
    asm volatile("cp.async.wait_group %0;" :: "n"(N) : "memory");
}
// cp.async with runtime src-size (0 => zero-fill, no read)
__device__ __forceinline__ void cp16z(uint32_t dst, const void* src, unsigned sz) {
    asm volatile("cp.async.cg.shared.global [%0], [%1], 16, %2;"
                 :: "r"(dst), "l"(src), "r"(sz) : "memory");
}

#define LDM4(r, a) \
    asm volatile("ldmatrix.sync.aligned.m8n8.x4.shared.b16 {%0,%1,%2,%3}, [%4];" \
                 : "=r"((r)[0]), "=r"((r)[1]), "=r"((r)[2]), "=r"((r)[3]) : "r"(a))

#define MMA(c, a, b) \
    asm volatile("mma.sync.aligned.m16n8k16.row.col.f32.bf16.bf16.f32 " \
                 "{%0,%1,%2,%3},{%4,%5,%6,%7},{%8,%9},{%0,%1,%2,%3};" \
                 : "+f"((c)[0]), "+f"((c)[1]), "+f"((c)[2]), "+f"((c)[3]) \
                 : "r"((a)[0]), "r"((a)[1]), "r"((a)[2]), "r"((a)[3]), \
                   "r"((b)[0]), "r"((b)[1]))

// ---------------------------------------------------------------------------
// Routing (species dtype probe: JAX x64-off silently emits int32)
// ---------------------------------------------------------------------------
__global__ void k_reset() {
    if (threadIdx.x < NSPEC) g_cnt[threadIdx.x] = 0;
    if (threadIdx.x == 0)    g_or_odd = 0;
}
__global__ void k_probe(const int* __restrict__ w) {
    int i = blockIdx.x * blockDim.x + threadIdx.x;   // odd-word index 0..32767
    int v = w[2 * i + 1];
    for (int o = 16; o > 0; o >>= 1) v |= __shfl_xor_sync(0xffffffffu, v, o);
    if ((threadIdx.x & 31) == 0 && v) atomicOr(&g_or_odd, 1);
}
__global__ void k_scatter(const int* __restrict__ w) {
    int i = blockIdx.x * blockDim.x + threadIdx.x;
    if (i >= NT) return;
    bool is64 = (g_or_odd == 0);
    int s = is64 ? w[2 * i] : w[i];
    if ((unsigned)s < NSPEC) {
        int p = atomicAdd(&g_cnt[s], 1);
        g_idx[s * NT + p] = i;
    }
}
__global__ void k_prefix() {
    if (threadIdx.x == 0) {
        int a = 0;
        for (int s = 0; s < NSPEC; s++) { g_off[s] = a; a += g_cnt[s]; }
    }
}

// ---------------------------------------------------------------------------
// Conversions: x -> bf16 hi/lo; W[s][k][n] -> Wt[s][n][k] bf16 hi/lo
// ---------------------------------------------------------------------------
__global__ void conv_x(const float* __restrict__ x) {
    size_t i = ((size_t)blockIdx.x * 256 + threadIdx.x) * 4;
    float4 v = *(const float4*)(x + i);
    __nv_bfloat16 h0 = __float2bfloat16(v.x), h1 = __float2bfloat16(v.y);
    __nv_bfloat16 h2 = __float2bfloat16(v.z), h3 = __float2bfloat16(v.w);
    __nv_bfloat16 l0 = __float2bfloat16(v.x - __bfloat162float(h0));
    __nv_bfloat16 l1 = __float2bfloat16(v.y - __bfloat162float(h1));
    __nv_bfloat16 l2 = __float2bfloat16(v.z - __bfloat162float(h2));
    __nv_bfloat16 l3 = __float2bfloat16(v.w - __bfloat162float(h3));
    uint2 ph, pl;
    ph.x = (uint32_t)__bfloat16_as_ushort(h0) | ((uint32_t)__bfloat16_as_ushort(h1) << 16);
    ph.y = (uint32_t)__bfloat16_as_ushort(h2) | ((uint32_t)__bfloat16_as_ushort(h3) << 16);
    pl.x = (uint32_t)__bfloat16_as_ushort(l0) | ((uint32_t)__bfloat16_as_ushort(l1) << 16);
    pl.y = (uint32_t)__bfloat16_as_ushort(l2) | ((uint32_t)__bfloat16_as_ushort(l3) << 16);
    ((uint2*)g_xh)[i / 4] = ph;
    ((uint2*)g_xl)[i / 4] = pl;
}

template<int KD, int ND>
__global__ void conv_w(const float* __restrict__ W,
                       __nv_bfloat16* __restrict__ Th,
                       __nv_bfloat16* __restrict__ Tl) {
    __shared__ float sm[32][33];
    int s = blockIdx.z, k0 = blockIdx.x * 32, n0 = blockIdx.y * 32;
    int tx = threadIdx.x, ty = threadIdx.y;   // (32, 8)
    const float* Wp = W + (size_t)s * KD * ND;
#pragma unroll
    for (int j = 0; j < 4; j++)
        sm[ty + j * 8][tx] = Wp[(size_t)(k0 + ty + j * 8) * ND + n0 + tx];
    __syncthreads();
#pragma unroll
    for (int j = 0; j < 4; j++) {
        int n = ty + j * 8;
        float v = sm[tx][n];
        __nv_bfloat16 h = __float2bfloat16(v);
        __nv_bfloat16 l = __float2bfloat16(v - __bfloat162float(h));
        size_t o = ((size_t)s * ND + n0 + n) * KD + k0 + tx;
        Th[o] = h; Tl[o] = l;
    }
}

// ---------------------------------------------------------------------------
// mma.sync split-bf16 GEMM over one species bucket.
//   Block tile 128(M) x 256(N), K chunks of 64. 8 warps: warp tile 64x64.
//   C = Ah*Bh + Ah*Bl + Al*Bh (fp32 accum) -- ~fp32 accuracy.
// Dynamic SMEM: 2 buffers x 96KB; each: Ah 16K | Al 16K | Bh 32K | Bl 32K,
//   rows of 64 bf16 (128B) with SW128 swizzle.
// ---------------------------------------------------------------------------
#define GEMM_SMEM 196608

template<int KT, int NDIM, bool GATHER_A, bool SCATTER_OUT, bool DO_SILU>
__global__ void __launch_bounds__(256, 1)
moe_gemm(const __nv_bfloat16* __restrict__ Ah, const __nv_bfloat16* __restrict__ Al,
         const __nv_bfloat16* __restrict__ Bh, const __nv_bfloat16* __restrict__ Bl,
         const float* __restrict__ bias,
         __nv_bfloat16* __restrict__ Oh, __nv_bfloat16* __restrict__ Ol,
         float* __restrict__ Of)
{
    constexpr int NC = KT / 64;
    extern __shared__ char dyn[];
    __shared__ int   tok[128];
    __shared__ float bsm[256];

    const int tid = threadIdx.x, wid = tid >> 5, lane = tid & 31;
    const int s   = blockIdx.z;
    const int cnt = g_cnt[s];
    const int m0  = blockIdx.x * 128;
    if (m0 >= cnt) return;
    const int n0    = blockIdx.y * 256;
    const int valid = min(128, cnt - m0);
    const int off   = g_off[s];
    const uint32_t sbase = s2u(dyn);

    for (int i = tid; i < 128; i += 256)
        tok[i] = (i < valid) ? g_idx[s * NT + m0 + i] : -1;
    bsm[tid] = bias[(size_t)s * NDIM + n0 + tid];
    __syncthreads();

    auto issue = [&](int c) {
        const int k0 = c * 64;
        const uint32_t bb = sbase + (uint32_t)(c & 1) * 98304u;
#pragma unroll
        for (int i = 0; i < 8; i++) {          // A: hi/lo x 128 rows x 8 units
            int t = tid + i * 256;
            int arr = t >> 10, row = (t >> 3) & 127, u = t & 7;
            int gr;
            if (GATHER_A) gr = tok[row];
            else          gr = (row < valid) ? (off + m0 + row) : -1;
            const __nv_bfloat16* src =
                (arr ? Al : Ah) + (size_t)max(gr, 0) * KT + k0 + u * 8;
            uint32_t dst = bb + (uint32_t)arr * 16384u + swz((uint32_t)row * 128u + u * 16u);
            cp16z(dst, src, (gr >= 0) ? 16u : 0u);
        }
#pragma unroll
        for (int i = 0; i < 16; i++) {         // B: hi/lo x 256 rows x 8 units
            int t = tid + i * 256;
            int arr = t >> 11, row = (t >> 3) & 255, u = t & 7;
            const __nv_bfloat16* src =
                (arr ? Bl : Bh) + ((size_t)s * NDIM + n0 + row) * KT + k0 + u * 8;
            uint32_t dst = bb + 32768u + (uint32_t)arr * 32768u
                         + swz((uint32_t)row * 128u + u * 16u);
            cp16z(dst, src, 16u);
        }
        CP_COMMIT();
    };

    float acc[4][8][4];
#pragma unroll
    for (int a = 0; a < 4; a++)
#pragma unroll
        for (int b = 0; b < 8; b++)
#pragma unroll
            for (int q = 0; q < 4; q++) acc[a][b][q] = 0.f;

    const int wm = wid & 1;            // M warp (0-1): 64 rows each
    const int wn = wid >> 1;           // N warp (0-3): 64 cols each
    const int ra = (lane & 7) + ((lane >> 3) & 1) * 8;   // A ldmatrix row
    const int ca = ((lane >> 4) & 1) * 8;                // A ldmatrix col (bf16)
    const int rb = (lane & 7) + ((lane >> 4) & 1) * 8;   // B ldmatrix row (n)
    const int cb = ((lane >> 3) & 1) * 8;                // B ldmatrix col (k)

    issue(0);
#pragma unroll 1
    for (int c = 0; c < NC; c++) {
        if (c + 1 < NC) { issue(c + 1); cp_wait<1>(); }
        else            { cp_wait<0>(); }
        __syncthreads();
        const uint32_t bb = sbase + (uint32_t)(c & 1) * 98304u;
#pragma unroll
        for (int ks = 0; ks < 4; ks++) {
            // Phase 1: hi*hi
            uint32_t af[4][4], bf[4][4];
#pragma unroll
            for (int mt = 0; mt < 4; mt++) {
                uint32_t o = (uint32_t)((wm * 64 + mt * 16 + ra) * 128
                                        + (ks * 16 + ca) * 2);
                LDM4(af[mt], bb + swz(o));
            }
#pragma unroll
            for (int np = 0; np < 4; np++) {
                uint32_t o = (uint32_t)((wn * 64 + np * 16 + rb) * 128
                                        + (ks * 16 + cb) * 2);
                LDM4(bf[np], bb + 32768u + swz(o));
            }
#pragma unroll
            for (int mt = 0; mt < 4; mt++)
#pragma unroll
                for (int nt = 0; nt < 8; nt++)
                    MMA(acc[mt][nt], af[mt], &bf[nt >> 1][(nt & 1) * 2]);

            // Phase 2: lo(A)*hi(B)  -- af stays live, alf is transient
            {
                uint32_t alf[4][4];
#pragma unroll
                for (int mt = 0; mt < 4; mt++) {
                    uint32_t o = (uint32_t)((wm * 64 + mt * 16 + ra) * 128
                                            + (ks * 16 + ca) * 2);
                    LDM4(alf[mt], bb + 16384u + swz(o));
                }
#pragma unroll
                for (int mt = 0; mt < 4; mt++)
#pragma unroll
                    for (int nt = 0; nt < 8; nt++)
                        MMA(acc[mt][nt], alf[mt], &bf[nt >> 1][(nt & 1) * 2]);
            }

            // Phase 3: hi(A)*lo(B)  -- bf dead, blf reuses its registers
            {
                uint32_t blf[4][4];
#pragma unroll
                for (int np = 0; np < 4; np++) {
                    uint32_t o = (uint32_t)((wn * 64 + np * 16 + rb) * 128
                                            + (ks * 16 + cb) * 2);
                    LDM4(blf[np], bb + 65536u + swz(o));
                }
#pragma unroll
                for (int mt = 0; mt < 4; mt++)
#pragma unroll
                    for (int nt = 0; nt < 8; nt++)
                        MMA(acc[mt][nt], af[mt], &blf[nt >> 1][(nt & 1) * 2]);
            }
        }
        __syncthreads();
    }

    // Epilogue: bias (+SiLU+split) and store. Acc row = wm*64+mt*16+gid(+8),
    // col = wn*64+nt*8+tig*2.
    const int gid = lane >> 2, tig = lane & 3;
#pragma unroll
    for (int mt = 0; mt < 4; mt++)
#pragma unroll
        for (int half = 0; half < 2; half++) {
            int lrow = wm * 64 + mt * 16 + gid + half * 8;
            if (lrow >= valid) continue;
            int orow = SCATTER_OUT ? tok[lrow] : (off + m0 + lrow);
#pragma unroll
            for (int nt = 0; nt < 8; nt++) {
                int col = wn * 64 + nt * 8 + tig * 2;
                float v0 = acc[mt][nt][half * 2 + 0] + bsm[col];
                float v1 = acc[mt][nt][half * 2 + 1] + bsm[col + 1];
                if (DO_SILU) {
                    v0 = v0 / (1.f + __expf(-v0));
                    v1 = v1 / (1.f + __expf(-v1));
                    __nv_bfloat16 h0 = __float2bfloat16(v0);
                    __nv_bfloat16 h1 = __float2bfloat16(v1);
                    __nv_bfloat16 l0 = __float2bfloat16(v0 - __bfloat162float(h0));
                    __nv_bfloat16 l1 = __float2bfloat16(v1 - __bfloat162float(h1));
                    uint32_t ph = (uint32_t)__bfloat16_as_ushort(h0)
                                | ((uint32_t)__bfloat16_as_ushort(h1) << 16);
                    uint32_t pl = (uint32_t)__bfloat16_as_ushort(l0)
                                | ((uint32_t)__bfloat16_as_ushort(l1) << 16);
                    *(uint32_t*)(Oh + (size_t)orow * NDIM + n0 + col) = ph;
                    *(uint32_t*)(Ol + (size_t)orow * NDIM + n0 + col) = pl;
                } else {
                    float2 v = make_float2(v0, v1);
                    *(float2*)(Of + (size_t)orow * NDIM + n0 + col) = v;
                }
            }
        }
}

// ---------------------------------------------------------------------------
// Launch: inputs: x, central_species, W1, b1, W2, b2
// ---------------------------------------------------------------------------
extern "C" void kernel_launch(void* const* d_in, const int* in_sizes, int n_in,
                              void* d_out, int out_size)
{
    const float* x   = (const float*)d_in[0];
    const int*   spw = (const int*)d_in[1];
    const float* W1  = (const float*)d_in[2];
    const float* b1  = (const float*)d_in[3];
    const float* W2  = (const float*)d_in[4];
    const float* b2  = (const float*)d_in[5];
    float*       out = (float*)d_out;

    __nv_bfloat16 *xh, *xl, *Hh, *Hl, *w1h, *w1l, *w2h, *w2l;
    cudaGetSymbolAddress((void**)&xh,  g_xh);
    cudaGetSymbolAddress((void**)&xl,  g_xl);
    cudaGetSymbolAddress((void**)&Hh,  g_Hh);
    cudaGetSymbolAddress((void**)&Hl,  g_Hl);
    cudaGetSymbolAddress((void**)&w1h, g_w1h);
    cudaGetSymbolAddress((void**)&w1l, g_w1l);
    cudaGetSymbolAddress((void**)&w2h, g_w2h);
    cudaGetSymbolAddress((void**)&w2l, g_w2l);

    cudaFuncSetAttribute(moe_gemm<DIN,  DHID, true,  false, true>,
                         cudaFuncAttributeMaxDynamicSharedMemorySize, GEMM_SMEM);
    cudaFuncSetAttribute(moe_gemm<DHID, DOUT, false, true,  false>,
                         cudaFuncAttributeMaxDynamicSharedMemorySize, GEMM_SMEM);

    k_reset  <<<1, 32>>>();
    k_probe  <<<128, 256>>>(spw);
    k_scatter<<<NT / 256, 256>>>(spw);
    k_prefix <<<1, 1>>>();

    conv_x<<<NT * DIN / 4 / 256, 256>>>(x);
    conv_w<DIN,  DHID><<<dim3(DIN / 32,  DHID / 32, NSPEC), dim3(32, 8)>>>(W1, w1h, w1l);
    conv_w<DHID, DOUT><<<dim3(DHID / 32, DOUT / 32, NSPEC), dim3(32, 8)>>>(W2, w2h, w2l);

    // GEMM1: H = silu(x @ W1[s] + b1[s]) -> compact bf16 hi/lo
    moe_gemm<DIN, DHID, true, false, true>
        <<<dim3(NT / 128, DHID / 256, NSPEC), 256, GEMM_SMEM>>>(
            xh, xl, w1h, w1l, b1, Hh, Hl, nullptr);

    // GEMM2: out = H @ W2[s] + b2[s] -> scatter fp32 by token
    moe_gemm<DHID, DOUT, false, true, false>
        <<<dim3(NT / 128, DOUT / 256, NSPEC), 256, GEMM_SMEM>>>(
            Hh, Hl, w2h, w2l, b2, nullptr, nullptr, out);
}

// round 7
// speedup vs baseline: 3.5697x; 1.2852x over previous
#include <cuda_runtime.h>
#include <cuda_fp16.h>
#include <stdint.h>
#include <math.h>

#define NT    65536
#define NSPEC 4
#define DIN   256
#define DHID  1024
#define DOUT  256

// ---------------------------------------------------------------------------
// Device-global scratch (allocation-free rule).
// ---------------------------------------------------------------------------
__device__ int g_cnt[NSPEC];
__device__ int g_off[NSPEC];
__device__ int g_or_odd;
__device__ int g_idx[NSPEC * NT];
__device__ __half g_xh[(size_t)NT * DIN];
__device__ __half g_xl[(size_t)NT * DIN];
__device__ __half g_Hh[(size_t)NT * DHID];
__device__ __half g_Hl[(size_t)NT * DHID];
__device__ __half g_w1[(size_t)NSPEC * DHID * DIN];   // [s][n][k] fp16
__device__ __half g_w2[(size_t)NSPEC * DOUT * DHID];

// ---------------------------------------------------------------------------
// Helpers
// ---------------------------------------------------------------------------
__device__ __forceinline__ uint32_t s2u(const void* p) {
    uint32_t a;
    asm("{ .reg .u64 t; cvta.to.shared.u64 t, %1; cvt.u32.u64 %0, t; }" : "=r"(a) : "l"(p));
    return a;
}
__device__ __forceinline__ uint32_t swz(uint32_t o) { return o ^ ((o >> 3) & 0x70u); }

#define CP_COMMIT() asm volatile("cp.async.commit_group;" ::: "memory")
template<int N> __device__ __forceinline__ void cp_wait() {
    asm volatile("cp.async.wait_group %0;" :: "n"(N) : "memory");
}
// cp.async with runtime src-size (0 => zero-fill, no read)
__device__ __forceinline__ void cp16z(uint32_t dst, const void* src, unsigned sz) {
    asm volatile("cp.async.cg.shared.global [%0], [%1], 16, %2;"
                 :: "r"(dst), "l"(src), "r"(sz) : "memory");
}

#define LDM4(r, a) \
    asm volatile("ldmatrix.sync.aligned.m8n8.x4.shared.b16 {%0,%1,%2,%3}, [%4];" \
                 : "=r"((r)[0]), "=r"((r)[1]), "=r"((r)[2]), "=r"((r)[3]) : "r"(a))

#define MMA(c, a, b) \
    asm volatile("mma.sync.aligned.m16n8k16.row.col.f32.f16.f16.f32 " \
                 "{%0,%1,%2,%3},{%4,%5,%6,%7},{%8,%9},{%0,%1,%2,%3};" \
                 : "+f"((c)[0]), "+f"((c)[1]), "+f"((c)[2]), "+f"((c)[3]) \
                 : "r"((a)[0]), "r"((a)[1]), "r"((a)[2]), "r"((a)[3]), \
                   "r"((b)[0]), "r"((b)[1]))

// ---------------------------------------------------------------------------
// Routing (species dtype probe: JAX x64-off silently emits int32)
// ---------------------------------------------------------------------------
__global__ void k_reset() {
    if (threadIdx.x < NSPEC) g_cnt[threadIdx.x] = 0;
    if (threadIdx.x == 0)    g_or_odd = 0;
}
__global__ void k_probe(const int* __restrict__ w) {
    int i = blockIdx.x * blockDim.x + threadIdx.x;   // odd-word index 0..32767
    int v = w[2 * i + 1];
    for (int o = 16; o > 0; o >>= 1) v |= __shfl_xor_sync(0xffffffffu, v, o);
    if ((threadIdx.x & 31) == 0 && v) atomicOr(&g_or_odd, 1);
}
__global__ void k_scatter(const int* __restrict__ w) {
    int i = blockIdx.x * blockDim.x + threadIdx.x;
    if (i >= NT) return;
    bool is64 = (g_or_odd == 0);
    int s = is64 ? w[2 * i] : w[i];
    if ((unsigned)s < NSPEC) {
        int p = atomicAdd(&g_cnt[s], 1);
        g_idx[s * NT + p] = i;
    }
}
__global__ void k_prefix() {
    if (threadIdx.x == 0) {
        int a = 0;
        for (int s = 0; s < NSPEC; s++) { g_off[s] = a; a += g_cnt[s]; }
    }
}

// ---------------------------------------------------------------------------
// Conversions: x -> fp16 hi/lo; W[s][k][n] -> Wt[s][n][k] single fp16
// ---------------------------------------------------------------------------
__global__ void conv_x(const float* __restrict__ x) {
    size_t i = ((size_t)blockIdx.x * 256 + threadIdx.x) * 4;
    float4 v = *(const float4*)(x + i);
    __half h0 = __float2half_rn(v.x), h1 = __float2half_rn(v.y);
    __half h2 = __float2half_rn(v.z), h3 = __float2half_rn(v.w);
    __half l0 = __float2half_rn(v.x - __half2float(h0));
    __half l1 = __float2half_rn(v.y - __half2float(h1));
    __half l2 = __float2half_rn(v.z - __half2float(h2));
    __half l3 = __float2half_rn(v.w - __half2float(h3));
    uint2 ph, pl;
    ph.x = (uint32_t)__half_as_ushort(h0) | ((uint32_t)__half_as_ushort(h1) << 16);
    ph.y = (uint32_t)__half_as_ushort(h2) | ((uint32_t)__half_as_ushort(h3) << 16);
    pl.x = (uint32_t)__half_as_ushort(l0) | ((uint32_t)__half_as_ushort(l1) << 16);
    pl.y = (uint32_t)__half_as_ushort(l2) | ((uint32_t)__half_as_ushort(l3) << 16);
    ((uint2*)g_xh)[i / 4] = ph;
    ((uint2*)g_xl)[i / 4] = pl;
}

template<int KD, int ND>
__global__ void conv_w(const float* __restrict__ W, __half* __restrict__ T) {
    __shared__ float sm[32][33];
    int s = blockIdx.z, k0 = blockIdx.x * 32, n0 = blockIdx.y * 32;
    int tx = threadIdx.x, ty = threadIdx.y;   // (32, 8)
    const float* Wp = W + (size_t)s * KD * ND;
#pragma unroll
    for (int j = 0; j < 4; j++)
        sm[ty + j * 8][tx] = Wp[(size_t)(k0 + ty + j * 8) * ND + n0 + tx];
    __syncthreads();
#pragma unroll
    for (int j = 0; j < 4; j++) {
        int n = ty + j * 8;
        T[((size_t)s * ND + n0 + n) * KD + k0 + tx] = __float2half_rn(sm[tx][n]);
    }
}

// ---------------------------------------------------------------------------
// mma.sync 2-pass fp16 GEMM over one species bucket.
//   Block tile 128(M) x 256(N), K chunks of 64. 8 warps: warp tile 64x64.
//   C = Ah*B + Al*B (fp32 accum); A = Ah+Al exact to 2^-22, B single fp16.
// Dynamic SMEM: 2 buffers x 64KB; each: Ah 16K | Al 16K | B 32K,
//   rows of 64 fp16 (128B) with SW128 swizzle.
// ---------------------------------------------------------------------------
#define GEMM_SMEM 131072

template<int KT, int NDIM, bool GATHER_A, bool SCATTER_OUT, bool DO_SILU>
__global__ void __launch_bounds__(256, 1)
moe_gemm(const __half* __restrict__ Ah, const __half* __restrict__ Al,
         const __half* __restrict__ B,
         const float* __restrict__ bias,
         __half* __restrict__ Oh, __half* __restrict__ Ol,
         float* __restrict__ Of)
{
    constexpr int NC = KT / 64;
    extern __shared__ char dyn[];
    __shared__ int   tok[128];
    __shared__ float bsm[256];

    const int tid = threadIdx.x, wid = tid >> 5, lane = tid & 31;
    const int s   = blockIdx.z;
    const int cnt = g_cnt[s];
    const int m0  = blockIdx.x * 128;
    if (m0 >= cnt) return;
    const int n0    = blockIdx.y * 256;
    const int valid = min(128, cnt - m0);
    const int off   = g_off[s];
    const uint32_t sbase = s2u(dyn);

    for (int i = tid; i < 128; i += 256)
        tok[i] = (i < valid) ? g_idx[s * NT + m0 + i] : -1;
    bsm[tid] = bias[(size_t)s * NDIM + n0 + tid];
    __syncthreads();

    auto issue = [&](int c) {
        const int k0 = c * 64;
        const uint32_t bb = sbase + (uint32_t)(c & 1) * 65536u;
#pragma unroll
        for (int i = 0; i < 8; i++) {          // A: hi/lo x 128 rows x 8 units
            int t = tid + i * 256;
            int arr = t >> 10, row = (t >> 3) & 127, u = t & 7;
            int gr;
            if (GATHER_A) gr = tok[row];
            else          gr = (row < valid) ? (off + m0 + row) : -1;
            const __half* src =
                (arr ? Al : Ah) + (size_t)max(gr, 0) * KT + k0 + u * 8;
            uint32_t dst = bb + (uint32_t)arr * 16384u + swz((uint32_t)row * 128u + u * 16u);
            cp16z(dst, src, (gr >= 0) ? 16u : 0u);
        }
#pragma unroll
        for (int i = 0; i < 8; i++) {          // B: 256 rows x 8 units
            int t = tid + i * 256;
            int row = t >> 3, u = t & 7;
            const __half* src = B + ((size_t)s * NDIM + n0 + row) * KT + k0 + u * 8;
            uint32_t dst = bb + 32768u + swz((uint32_t)row * 128u + u * 16u);
            cp16z(dst, src, 16u);
        }
        CP_COMMIT();
    };

    float acc[4][8][4];
#pragma unroll
    for (int a = 0; a < 4; a++)
#pragma unroll
        for (int b = 0; b < 8; b++)
#pragma unroll
            for (int q = 0; q < 4; q++) acc[a][b][q] = 0.f;

    const int wm = wid & 1;            // M warp (0-1): 64 rows each
    const int wn = wid >> 1;           // N warp (0-3): 64 cols each
    const int ra = (lane & 7) + ((lane >> 3) & 1) * 8;   // A ldmatrix row
    const int ca = ((lane >> 4) & 1) * 8;                // A ldmatrix col (fp16)
    const int rb = (lane & 7) + ((lane >> 4) & 1) * 8;   // B ldmatrix row (n)
    const int cb = ((lane >> 3) & 1) * 8;                // B ldmatrix col (k)

    issue(0);
#pragma unroll 1
    for (int c = 0; c < NC; c++) {
        if (c + 1 < NC) { issue(c + 1); cp_wait<1>(); }
        else            { cp_wait<0>(); }
        __syncthreads();
        const uint32_t bb = sbase + (uint32_t)(c & 1) * 65536u;
#pragma unroll
        for (int ks = 0; ks < 4; ks++) {
            // Phase 1: Ah * B
            uint32_t af[4][4], bf[4][4];
#pragma unroll
            for (int mt = 0; mt < 4; mt++) {
                uint32_t o = (uint32_t)((wm * 64 + mt * 16 + ra) * 128
                                        + (ks * 16 + ca) * 2);
                LDM4(af[mt], bb + swz(o));
            }
#pragma unroll
            for (int np = 0; np < 4; np++) {
                uint32_t o = (uint32_t)((wn * 64 + np * 16 + rb) * 128
                                        + (ks * 16 + cb) * 2);
                LDM4(bf[np], bb + 32768u + swz(o));
            }
#pragma unroll
            for (int mt = 0; mt < 4; mt++)
#pragma unroll
                for (int nt = 0; nt < 8; nt++)
                    MMA(acc[mt][nt], af[mt], &bf[nt >> 1][(nt & 1) * 2]);

            // Phase 2: Al * B (af dead; alf reuses its registers)
            {
                uint32_t alf[4][4];
#pragma unroll
                for (int mt = 0; mt < 4; mt++) {
                    uint32_t o = (uint32_t)((wm * 64 + mt * 16 + ra) * 128
                                            + (ks * 16 + ca) * 2);
                    LDM4(alf[mt], bb + 16384u + swz(o));
                }
#pragma unroll
                for (int mt = 0; mt < 4; mt++)
#pragma unroll
                    for (int nt = 0; nt < 8; nt++)
                        MMA(acc[mt][nt], alf[mt], &bf[nt >> 1][(nt & 1) * 2]);
            }
        }
        __syncthreads();
    }

    // Epilogue: bias (+SiLU+fp16 split) and store. Row = wm*64+mt*16+gid(+8),
    // col = wn*64+nt*8+tig*2.
    const int gid = lane >> 2, tig = lane & 3;
#pragma unroll
    for (int mt = 0; mt < 4; mt++)
#pragma unroll
        for (int half = 0; half < 2; half++) {
            int lrow = wm * 64 + mt * 16 + gid + half * 8;
            if (lrow >= valid) continue;
            int orow = SCATTER_OUT ? tok[lrow] : (off + m0 + lrow);
#pragma unroll
            for (int nt = 0; nt < 8; nt++) {
                int col = wn * 64 + nt * 8 + tig * 2;
                float v0 = acc[mt][nt][half * 2 + 0] + bsm[col];
                float v1 = acc[mt][nt][half * 2 + 1] + bsm[col + 1];
                if (DO_SILU) {
                    v0 = v0 / (1.f + __expf(-v0));
                    v1 = v1 / (1.f + __expf(-v1));
                    __half h0 = __float2half_rn(v0);
                    __half h1 = __float2half_rn(v1);
                    __half l0 = __float2half_rn(v0 - __half2float(h0));
                    __half l1 = __float2half_rn(v1 - __half2float(h1));
                    uint32_t ph = (uint32_t)__half_as_ushort(h0)
                                | ((uint32_t)__half_as_ushort(h1) << 16);
                    uint32_t pl = (uint32_t)__half_as_ushort(l0)
                                | ((uint32_t)__half_as_ushort(l1) << 16);
                    *(uint32_t*)(Oh + (size_t)orow * NDIM + n0 + col) = ph;
                    *(uint32_t*)(Ol + (size_t)orow * NDIM + n0 + col) = pl;
                } else {
                    float2 v = make_float2(v0, v1);
                    *(float2*)(Of + (size_t)orow * NDIM + n0 + col) = v;
                }
            }
        }
}

// ---------------------------------------------------------------------------
// Launch: inputs: x, central_species, W1, b1, W2, b2
// ---------------------------------------------------------------------------
extern "C" void kernel_launch(void* const* d_in, const int* in_sizes, int n_in,
                              void* d_out, int out_size)
{
    const float* x   = (const float*)d_in[0];
    const int*   spw = (const int*)d_in[1];
    const float* W1  = (const float*)d_in[2];
    const float* b1  = (const float*)d_in[3];
    const float* W2  = (const float*)d_in[4];
    const float* b2  = (const float*)d_in[5];
    float*       out = (float*)d_out;

    __half *xh, *xl, *Hh, *Hl, *w1, *w2;
    cudaGetSymbolAddress((void**)&xh, g_xh);
    cudaGetSymbolAddress((void**)&xl, g_xl);
    cudaGetSymbolAddress((void**)&Hh, g_Hh);
    cudaGetSymbolAddress((void**)&Hl, g_Hl);
    cudaGetSymbolAddress((void**)&w1, g_w1);
    cudaGetSymbolAddress((void**)&w2, g_w2);

    cudaFuncSetAttribute(moe_gemm<DIN,  DHID, true,  false, true>,
                         cudaFuncAttributeMaxDynamicSharedMemorySize, GEMM_SMEM);
    cudaFuncSetAttribute(moe_gemm<DHID, DOUT, false, true,  false>,
                         cudaFuncAttributeMaxDynamicSharedMemorySize, GEMM_SMEM);

    k_reset  <<<1, 32>>>();
    k_probe  <<<128, 256>>>(spw);
    k_scatter<<<NT / 256, 256>>>(spw);
    k_prefix <<<1, 1>>>();

    conv_x<<<NT * DIN / 4 / 256, 256>>>(x);
    conv_w<DIN,  DHID><<<dim3(DIN / 32,  DHID / 32, NSPEC), dim3(32, 8)>>>(W1, w1);
    conv_w<DHID, DOUT><<<dim3(DHID / 32, DOUT / 32, NSPEC), dim3(32, 8)>>>(W2, w2);

    // GEMM1: H = silu(x @ W1[s] + b1[s]) -> compact fp16 hi/lo
    moe_gemm<DIN, DHID, true, false, true>
        <<<dim3(NT / 128, DHID / 256, NSPEC), 256, GEMM_SMEM>>>(
            xh, xl, w1, b1, Hh, Hl, nullptr);

    // GEMM2: out = H @ W2[s] + b2[s] -> scatter fp32 by token
    moe_gemm<DHID, DOUT, false, true, false>
        <<<dim3(NT / 128, DOUT / 256, NSPEC), 256, GEMM_SMEM>>>(
            Hh, Hl, w2, b2, nullptr, nullptr, out);
}

// round 8
// speedup vs baseline: 5.0337x; 1.4101x over previous
#include <cuda_runtime.h>
#include <cuda_fp16.h>
#include <stdint.h>
#include <math.h>

#define NT    65536
#define NSPEC 4
#define DIN   256
#define DHID  1024
#define DOUT  256

// ---------------------------------------------------------------------------
// Device-global scratch (allocation-free rule).
// ---------------------------------------------------------------------------
__device__ int g_cnt[NSPEC];
__device__ int g_off[NSPEC];
__device__ int g_or_odd;
__device__ int g_idx[NSPEC * NT];
__device__ __half g_x16[(size_t)NT * DIN];
__device__ __half g_H16[(size_t)NT * DHID];
__device__ __half g_w1[(size_t)NSPEC * DHID * DIN];   // [s][n][k] fp16
__device__ __half g_w2[(size_t)NSPEC * DOUT * DHID];

// ---------------------------------------------------------------------------
// Helpers
// ---------------------------------------------------------------------------
__device__ __forceinline__ uint32_t s2u(const void* p) {
    uint32_t a;
    asm("{ .reg .u64 t; cvta.to.shared.u64 t, %1; cvt.u32.u64 %0, t; }" : "=r"(a) : "l"(p));
    return a;
}
__device__ __forceinline__ uint32_t swz(uint32_t o) { return o ^ ((o >> 3) & 0x70u); }

#define CP_COMMIT() asm volatile("cp.async.commit_group;" ::: "memory")
template<int N> __device__ __forceinline__ void cp_wait() {
    asm volatile("cp.async.wait_group %0;" :: "n"(N) : "memory");
}
// cp.async with runtime src-size (0 => zero-fill, no read)
__device__ __forceinline__ void cp16z(uint32_t dst, const void* src, unsigned sz) {
    asm volatile("cp.async.cg.shared.global [%0], [%1], 16, %2;"
                 :: "r"(dst), "l"(src), "r"(sz) : "memory");
}

#define LDM4(r, a) \
    asm volatile("ldmatrix.sync.aligned.m8n8.x4.shared.b16 {%0,%1,%2,%3}, [%4];" \
                 : "=r"((r)[0]), "=r"((r)[1]), "=r"((r)[2]), "=r"((r)[3]) : "r"(a))

#define MMA(c, a, b) \
    asm volatile("mma.sync.aligned.m16n8k16.row.col.f32.f16.f16.f32 " \
                 "{%0,%1,%2,%3},{%4,%5,%6,%7},{%8,%9},{%0,%1,%2,%3};" \
                 : "+f"((c)[0]), "+f"((c)[1]), "+f"((c)[2]), "+f"((c)[3]) \
                 : "r"((a)[0]), "r"((a)[1]), "r"((a)[2]), "r"((a)[3]), \
                   "r"((b)[0]), "r"((b)[1]))

// ---------------------------------------------------------------------------
// Routing (species dtype probe: JAX x64-off silently emits int32)
// ---------------------------------------------------------------------------
__global__ void k_reset() {
    if (threadIdx.x < NSPEC) g_cnt[threadIdx.x] = 0;
    if (threadIdx.x == 0)    g_or_odd = 0;
}
__global__ void k_probe(const int* __restrict__ w) {
    int i = blockIdx.x * blockDim.x + threadIdx.x;   // odd-word index 0..32767
    int v = w[2 * i + 1];
    for (int o = 16; o > 0; o >>= 1) v |= __shfl_xor_sync(0xffffffffu, v, o);
    if ((threadIdx.x & 31) == 0 && v) atomicOr(&g_or_odd, 1);
}
__global__ void k_scatter(const int* __restrict__ w) {
    int i = blockIdx.x * blockDim.x + threadIdx.x;
    if (i >= NT) return;
    bool is64 = (g_or_odd == 0);
    int s = is64 ? w[2 * i] : w[i];
    if ((unsigned)s < NSPEC) {
        int p = atomicAdd(&g_cnt[s], 1);
        g_idx[s * NT + p] = i;
    }
}
__global__ void k_prefix() {
    if (threadIdx.x == 0) {
        int a = 0;
        for (int s = 0; s < NSPEC; s++) { g_off[s] = a; a += g_cnt[s]; }
    }
}

// ---------------------------------------------------------------------------
// Conversions: x -> fp16; W[s][k][n] -> Wt[s][n][k] fp16
// ---------------------------------------------------------------------------
__global__ void conv_x(const float* __restrict__ x) {
    size_t i = ((size_t)blockIdx.x * 256 + threadIdx.x) * 4;
    float4 v = *(const float4*)(x + i);
    uint2 p;
    p.x = (uint32_t)__half_as_ushort(__float2half_rn(v.x))
        | ((uint32_t)__half_as_ushort(__float2half_rn(v.y)) << 16);
    p.y = (uint32_t)__half_as_ushort(__float2half_rn(v.z))
        | ((uint32_t)__half_as_ushort(__float2half_rn(v.w)) << 16);
    ((uint2*)g_x16)[i / 4] = p;
}

template<int KD, int ND>
__global__ void conv_w(const float* __restrict__ W, __half* __restrict__ T) {
    __shared__ float sm[32][33];
    int s = blockIdx.z, k0 = blockIdx.x * 32, n0 = blockIdx.y * 32;
    int tx = threadIdx.x, ty = threadIdx.y;   // (32, 8)
    const float* Wp = W + (size_t)s * KD * ND;
#pragma unroll
    for (int j = 0; j < 4; j++)
        sm[ty + j * 8][tx] = Wp[(size_t)(k0 + ty + j * 8) * ND + n0 + tx];
    __syncthreads();
#pragma unroll
    for (int j = 0; j < 4; j++) {
        int n = ty + j * 8;
        T[((size_t)s * ND + n0 + n) * KD + k0 + tx] = __float2half_rn(sm[tx][n]);
    }
}

// ---------------------------------------------------------------------------
// mma.sync fp16 GEMM over one species bucket (single-pass).
//   Block tile 128(M) x 256(N), K chunks of 64. 8 warps: warp tile 64x64.
// Dynamic SMEM: 2 buffers x 48KB; each: A 16K | B 32K,
//   rows of 64 fp16 (128B) with SW128 swizzle.
// ---------------------------------------------------------------------------
#define GEMM_SMEM 98304

template<int KT, int NDIM, bool GATHER_A, bool SCATTER_OUT, bool DO_SILU>
__global__ void __launch_bounds__(256, 1)
moe_gemm(const __half* __restrict__ A, const __half* __restrict__ B,
         const float* __restrict__ bias,
         __half* __restrict__ O16, float* __restrict__ Of)
{
    constexpr int NC = KT / 64;
    extern __shared__ char dyn[];
    __shared__ int   tok[128];
    __shared__ float bsm[256];

    const int tid = threadIdx.x, wid = tid >> 5, lane = tid & 31;
    const int s   = blockIdx.z;
    const int cnt = g_cnt[s];
    const int m0  = blockIdx.x * 128;
    if (m0 >= cnt) return;
    const int n0    = blockIdx.y * 256;
    const int valid = min(128, cnt - m0);
    const int off   = g_off[s];
    const uint32_t sbase = s2u(dyn);

    for (int i = tid; i < 128; i += 256)
        tok[i] = (i < valid) ? g_idx[s * NT + m0 + i] : -1;
    bsm[tid] = bias[(size_t)s * NDIM + n0 + tid];
    __syncthreads();

    auto issue = [&](int c) {
        const int k0 = c * 64;
        const uint32_t bb = sbase + (uint32_t)(c & 1) * 49152u;
#pragma unroll
        for (int i = 0; i < 4; i++) {          // A: 128 rows x 8 units
            int t = tid + i * 256;
            int row = t >> 3, u = t & 7;
            int gr;
            if (GATHER_A) gr = tok[row];
            else          gr = (row < valid) ? (off + m0 + row) : -1;
            const __half* src = A + (size_t)max(gr, 0) * KT + k0 + u * 8;
            uint32_t dst = bb + swz((uint32_t)row * 128u + u * 16u);
            cp16z(dst, src, (gr >= 0) ? 16u : 0u);
        }
#pragma unroll
        for (int i = 0; i < 8; i++) {          // B: 256 rows x 8 units
            int t = tid + i * 256;
            int row = t >> 3, u = t & 7;
            const __half* src = B + ((size_t)s * NDIM + n0 + row) * KT + k0 + u * 8;
            uint32_t dst = bb + 16384u + swz((uint32_t)row * 128u + u * 16u);
            cp16z(dst, src, 16u);
        }
        CP_COMMIT();
    };

    float acc[4][8][4];
#pragma unroll
    for (int a = 0; a < 4; a++)
#pragma unroll
        for (int b = 0; b < 8; b++)
#pragma unroll
            for (int q = 0; q < 4; q++) acc[a][b][q] = 0.f;

    const int wm = wid & 1;            // M warp (0-1): 64 rows each
    const int wn = wid >> 1;           // N warp (0-3): 64 cols each
    const int ra = (lane & 7) + ((lane >> 3) & 1) * 8;   // A ldmatrix row
    const int ca = ((lane >> 4) & 1) * 8;                // A ldmatrix col (fp16)
    const int rb = (lane & 7) + ((lane >> 4) & 1) * 8;   // B ldmatrix row (n)
    const int cb = ((lane >> 3) & 1) * 8;                // B ldmatrix col (k)

    issue(0);
#pragma unroll 1
    for (int c = 0; c < NC; c++) {
        if (c + 1 < NC) { issue(c + 1); cp_wait<1>(); }
        else            { cp_wait<0>(); }
        __syncthreads();
        const uint32_t bb = sbase + (uint32_t)(c & 1) * 49152u;
#pragma unroll
        for (int ks = 0; ks < 4; ks++) {
            uint32_t af[4][4], bf[4][4];
#pragma unroll
            for (int mt = 0; mt < 4; mt++) {
                uint32_t o = (uint32_t)((wm * 64 + mt * 16 + ra) * 128
                                        + (ks * 16 + ca) * 2);
                LDM4(af[mt], bb + swz(o));
            }
#pragma unroll
            for (int np = 0; np < 4; np++) {
                uint32_t o = (uint32_t)((wn * 64 + np * 16 + rb) * 128
                                        + (ks * 16 + cb) * 2);
                LDM4(bf[np], bb + 16384u + swz(o));
            }
#pragma unroll
            for (int mt = 0; mt < 4; mt++)
#pragma unroll
                for (int nt = 0; nt < 8; nt++)
                    MMA(acc[mt][nt], af[mt], &bf[nt >> 1][(nt & 1) * 2]);
        }
        __syncthreads();
    }

    // Epilogue: bias (+SiLU) and store. Row = wm*64+mt*16+gid(+8),
    // col = wn*64+nt*8+tig*2.
    const int gid = lane >> 2, tig = lane & 3;
#pragma unroll
    for (int mt = 0; mt < 4; mt++)
#pragma unroll
        for (int half = 0; half < 2; half++) {
            int lrow = wm * 64 + mt * 16 + gid + half * 8;
            if (lrow >= valid) continue;
            int orow = SCATTER_OUT ? tok[lrow] : (off + m0 + lrow);
#pragma unroll
            for (int nt = 0; nt < 8; nt++) {
                int col = wn * 64 + nt * 8 + tig * 2;
                float v0 = acc[mt][nt][half * 2 + 0] + bsm[col];
                float v1 = acc[mt][nt][half * 2 + 1] + bsm[col + 1];
                if (DO_SILU) {
                    v0 = v0 / (1.f + __expf(-v0));
                    v1 = v1 / (1.f + __expf(-v1));
                    uint32_t p = (uint32_t)__half_as_ushort(__float2half_rn(v0))
                               | ((uint32_t)__half_as_ushort(__float2half_rn(v1)) << 16);
                    *(uint32_t*)(O16 + (size_t)orow * NDIM + n0 + col) = p;
                } else {
                    float2 v = make_float2(v0, v1);
                    *(float2*)(Of + (size_t)orow * NDIM + n0 + col) = v;
                }
            }
        }
}

// ---------------------------------------------------------------------------
// Launch: inputs: x, central_species, W1, b1, W2, b2
// ---------------------------------------------------------------------------
extern "C" void kernel_launch(void* const* d_in, const int* in_sizes, int n_in,
                              void* d_out, int out_size)
{
    const float* x   = (const float*)d_in[0];
    const int*   spw = (const int*)d_in[1];
    const float* W1  = (const float*)d_in[2];
    const float* b1  = (const float*)d_in[3];
    const float* W2  = (const float*)d_in[4];
    const float* b2  = (const float*)d_in[5];
    float*       out = (float*)d_out;

    __half *x16, *H16, *w1, *w2;
    cudaGetSymbolAddress((void**)&x16, g_x16);
    cudaGetSymbolAddress((void**)&H16, g_H16);
    cudaGetSymbolAddress((void**)&w1,  g_w1);
    cudaGetSymbolAddress((void**)&w2,  g_w2);

    cudaFuncSetAttribute(moe_gemm<DIN,  DHID, true,  false, true>,
                         cudaFuncAttributeMaxDynamicSharedMemorySize, GEMM_SMEM);
    cudaFuncSetAttribute(moe_gemm<DHID, DOUT, false, true,  false>,
                         cudaFuncAttributeMaxDynamicSharedMemorySize, GEMM_SMEM);

    k_reset  <<<1, 32>>>();
    k_probe  <<<128, 256>>>(spw);
    k_scatter<<<NT / 256, 256>>>(spw);
    k_prefix <<<1, 1>>>();

    conv_x<<<NT * DIN / 4 / 256, 256>>>(x);
    conv_w<DIN,  DHID><<<dim3(DIN / 32,  DHID / 32, NSPEC), dim3(32, 8)>>>(W1, w1);
    conv_w<DHID, DOUT><<<dim3(DHID / 32, DOUT / 32, NSPEC), dim3(32, 8)>>>(W2, w2);

    // GEMM1: H = silu(x @ W1[s] + b1[s]) -> compact fp16
    moe_gemm<DIN, DHID, true, false, true>
        <<<dim3(NT / 128, DHID / 256, NSPEC), 256, GEMM_SMEM>>>(
            x16, w1, b1, H16, nullptr);

    // GEMM2: out = H @ W2[s] + b2[s] -> scatter fp32 by token
    moe_gemm<DHID, DOUT, false, true, false>
        <<<dim3(NT / 128, DOUT / 256, NSPEC), 256, GEMM_SMEM>>>(
            H16, w2, b2, nullptr, out);
}

// round 9
// speedup vs baseline: 6.3517x; 1.2618x over previous
#include <cuda_runtime.h>
#include <cuda_fp16.h>
#include <stdint.h>
#include <math.h>

#define NT    65536
#define NSPEC 4
#define DIN   256
#define DHID  1024
#define DOUT  256

// ---------------------------------------------------------------------------
// Device-global scratch (allocation-free rule).
// ---------------------------------------------------------------------------
__device__ int g_cnt[NSPEC];
__device__ int g_off[NSPEC];
__device__ int g_or_odd;
__device__ int g_idx[NSPEC * NT];
__device__ __half g_x16[(size_t)NT * DIN];
__device__ __half g_H16[(size_t)NT * DHID];
__device__ __half g_w1[(size_t)NSPEC * DHID * DIN];   // [s][n][k] fp16
__device__ __half g_w2[(size_t)NSPEC * DOUT * DHID];

// ---------------------------------------------------------------------------
// Helpers
// ---------------------------------------------------------------------------
__device__ __forceinline__ uint32_t s2u(const void* p) {
    uint32_t a;
    asm("{ .reg .u64 t; cvta.to.shared.u64 t, %1; cvt.u32.u64 %0, t; }" : "=r"(a) : "l"(p));
    return a;
}
__device__ __forceinline__ uint32_t swz(uint32_t o) { return o ^ ((o >> 3) & 0x70u); }

#define CP_COMMIT() asm volatile("cp.async.commit_group;" ::: "memory")
template<int N> __device__ __forceinline__ void cp_wait() {
    asm volatile("cp.async.wait_group %0;" :: "n"(N) : "memory");
}
// cp.async with runtime src-size (0 => zero-fill, no read)
__device__ __forceinline__ void cp16z(uint32_t dst, const void* src, unsigned sz) {
    asm volatile("cp.async.cg.shared.global [%0], [%1], 16, %2;"
                 :: "r"(dst), "l"(src), "r"(sz) : "memory");
}

#define LDM4(r, a) \
    asm volatile("ldmatrix.sync.aligned.m8n8.x4.shared.b16 {%0,%1,%2,%3}, [%4];" \
                 : "=r"((r)[0]), "=r"((r)[1]), "=r"((r)[2]), "=r"((r)[3]) : "r"(a))

#define MMA(c, a, b) \
    asm volatile("mma.sync.aligned.m16n8k16.row.col.f32.f16.f16.f32 " \
                 "{%0,%1,%2,%3},{%4,%5,%6,%7},{%8,%9},{%0,%1,%2,%3};" \
                 : "+f"((c)[0]), "+f"((c)[1]), "+f"((c)[2]), "+f"((c)[3]) \
                 : "r"((a)[0]), "r"((a)[1]), "r"((a)[2]), "r"((a)[3]), \
                   "r"((b)[0]), "r"((b)[1]))

// ---------------------------------------------------------------------------
// Routing (species dtype probe: JAX x64-off silently emits int32)
// ---------------------------------------------------------------------------
__global__ void k_reset() {
    if (threadIdx.x < NSPEC) g_cnt[threadIdx.x] = 0;
    if (threadIdx.x == 0)    g_or_odd = 0;
}
__global__ void k_probe(const int* __restrict__ w) {
    int i = blockIdx.x * blockDim.x + threadIdx.x;   // odd-word index 0..32767
    int v = w[2 * i + 1];
    for (int o = 16; o > 0; o >>= 1) v |= __shfl_xor_sync(0xffffffffu, v, o);
    if ((threadIdx.x & 31) == 0 && v) atomicOr(&g_or_odd, 1);
}
__global__ void k_scatter(const int* __restrict__ w) {
    int i = blockIdx.x * blockDim.x + threadIdx.x;
    if (i >= NT) return;
    bool is64 = (g_or_odd == 0);
    int s = is64 ? w[2 * i] : w[i];
    if ((unsigned)s < NSPEC) {
        int p = atomicAdd(&g_cnt[s], 1);
        g_idx[s * NT + p] = i;
    }
}
__global__ void k_prefix() {
    if (threadIdx.x == 0) {
        int a = 0;
        for (int s = 0; s < NSPEC; s++) { g_off[s] = a; a += g_cnt[s]; }
    }
}

// ---------------------------------------------------------------------------
// Conversions: x -> fp16; W[s][k][n] -> Wt[s][n][k] fp16
// ---------------------------------------------------------------------------
__global__ void conv_x(const float* __restrict__ x) {
    size_t i = ((size_t)blockIdx.x * 256 + threadIdx.x) * 4;
    float4 v = *(const float4*)(x + i);
    uint2 p;
    p.x = (uint32_t)__half_as_ushort(__float2half_rn(v.x))
        | ((uint32_t)__half_as_ushort(__float2half_rn(v.y)) << 16);
    p.y = (uint32_t)__half_as_ushort(__float2half_rn(v.z))
        | ((uint32_t)__half_as_ushort(__float2half_rn(v.w)) << 16);
    ((uint2*)g_x16)[i / 4] = p;
}

template<int KD, int ND>
__global__ void conv_w(const float* __restrict__ W, __half* __restrict__ T) {
    __shared__ float sm[32][33];
    int s = blockIdx.z, k0 = blockIdx.x * 32, n0 = blockIdx.y * 32;
    int tx = threadIdx.x, ty = threadIdx.y;   // (32, 8)
    const float* Wp = W + (size_t)s * KD * ND;
#pragma unroll
    for (int j = 0; j < 4; j++)
        sm[ty + j * 8][tx] = Wp[(size_t)(k0 + ty + j * 8) * ND + n0 + tx];
    __syncthreads();
#pragma unroll
    for (int j = 0; j < 4; j++) {
        int n = ty + j * 8;
        T[((size_t)s * ND + n0 + n) * KD + k0 + tx] = __float2half_rn(sm[tx][n]);
    }
}

// ---------------------------------------------------------------------------
// mma.sync fp16 GEMM over one species bucket (single-pass).
//   Block tile 128(M) x 128(N), K chunks of 64. 8 warps: warp tile 64x32.
//   Occupancy 2 CTAs/SM: prologue/epilogue/sync bubbles of one CTA are
//   covered by the co-resident CTA's MMA stream.
// Dynamic SMEM: 2 stages x 32KB; each: A 16K | B 16K,
//   rows of 64 fp16 (128B) with SW128 swizzle.
// ---------------------------------------------------------------------------
#define GEMM_SMEM 65536

template<int KT, int NDIM, bool GATHER_A, bool SCATTER_OUT, bool DO_SILU>
__global__ void __launch_bounds__(256, 2)
moe_gemm(const __half* __restrict__ A, const __half* __restrict__ B,
         const float* __restrict__ bias,
         __half* __restrict__ O16, float* __restrict__ Of)
{
    constexpr int NC = KT / 64;
    extern __shared__ char dyn[];
    __shared__ int   tok[128];
    __shared__ float bsm[128];

    const int tid = threadIdx.x, wid = tid >> 5, lane = tid & 31;
    const int s   = blockIdx.z;
    const int cnt = g_cnt[s];
    const int m0  = blockIdx.x * 128;
    if (m0 >= cnt) return;
    const int n0    = blockIdx.y * 128;
    const int valid = min(128, cnt - m0);
    const int off   = g_off[s];
    const uint32_t sbase = s2u(dyn);

    for (int i = tid; i < 128; i += 256)
        tok[i] = (i < valid) ? g_idx[s * NT + m0 + i] : -1;
    if (tid < 128) bsm[tid] = bias[(size_t)s * NDIM + n0 + tid];
    __syncthreads();

    auto issue = [&](int c) {
        const int k0 = c * 64;
        const uint32_t bb = sbase + (uint32_t)(c & 1) * 32768u;
#pragma unroll
        for (int i = 0; i < 4; i++) {          // A: 128 rows x 8 units
            int t = tid + i * 256;
            int row = t >> 3, u = t & 7;
            int gr;
            if (GATHER_A) gr = tok[row];
            else          gr = (row < valid) ? (off + m0 + row) : -1;
            const __half* src = A + (size_t)max(gr, 0) * KT + k0 + u * 8;
            uint32_t dst = bb + swz((uint32_t)row * 128u + u * 16u);
            cp16z(dst, src, (gr >= 0) ? 16u : 0u);
        }
#pragma unroll
        for (int i = 0; i < 4; i++) {          // B: 128 rows x 8 units
            int t = tid + i * 256;
            int row = t >> 3, u = t & 7;
            const __half* src = B + ((size_t)s * NDIM + n0 + row) * KT + k0 + u * 8;
            uint32_t dst = bb + 16384u + swz((uint32_t)row * 128u + u * 16u);
            cp16z(dst, src, 16u);
        }
        CP_COMMIT();
    };

    float acc[4][4][4];
#pragma unroll
    for (int a = 0; a < 4; a++)
#pragma unroll
        for (int b = 0; b < 4; b++)
#pragma unroll
            for (int q = 0; q < 4; q++) acc[a][b][q] = 0.f;

    const int wm = wid & 1;            // M warp (0-1): 64 rows each
    const int wn = wid >> 1;           // N warp (0-3): 32 cols each
    const int ra = (lane & 7) + ((lane >> 3) & 1) * 8;   // A ldmatrix row
    const int ca = ((lane >> 4) & 1) * 8;                // A ldmatrix col (fp16)
    const int rb = (lane & 7) + ((lane >> 4) & 1) * 8;   // B ldmatrix row (n)
    const int cb = ((lane >> 3) & 1) * 8;                // B ldmatrix col (k)

    issue(0);
#pragma unroll 1
    for (int c = 0; c < NC; c++) {
        if (c + 1 < NC) { issue(c + 1); cp_wait<1>(); }
        else            { cp_wait<0>(); }
        __syncthreads();
        const uint32_t bb = sbase + (uint32_t)(c & 1) * 32768u;
#pragma unroll
        for (int ks = 0; ks < 4; ks++) {
            uint32_t af[4][4], bf[2][4];
#pragma unroll
            for (int mt = 0; mt < 4; mt++) {
                uint32_t o = (uint32_t)((wm * 64 + mt * 16 + ra) * 128
                                        + (ks * 16 + ca) * 2);
                LDM4(af[mt], bb + swz(o));
            }
#pragma unroll
            for (int np = 0; np < 2; np++) {
                uint32_t o = (uint32_t)((wn * 32 + np * 16 + rb) * 128
                                        + (ks * 16 + cb) * 2);
                LDM4(bf[np], bb + 16384u + swz(o));
            }
#pragma unroll
            for (int mt = 0; mt < 4; mt++)
#pragma unroll
                for (int nt = 0; nt < 4; nt++)
                    MMA(acc[mt][nt], af[mt], &bf[nt >> 1][(nt & 1) * 2]);
        }
        __syncthreads();
    }

    // Epilogue: bias (+SiLU) and store. Row = wm*64+mt*16+gid(+8),
    // col = wn*32+nt*8+tig*2.
    const int gid = lane >> 2, tig = lane & 3;
#pragma unroll
    for (int mt = 0; mt < 4; mt++)
#pragma unroll
        for (int half = 0; half < 2; half++) {
            int lrow = wm * 64 + mt * 16 + gid + half * 8;
            if (lrow >= valid) continue;
            int orow = SCATTER_OUT ? tok[lrow] : (off + m0 + lrow);
#pragma unroll
            for (int nt = 0; nt < 4; nt++) {
                int col = wn * 32 + nt * 8 + tig * 2;
                float v0 = acc[mt][nt][half * 2 + 0] + bsm[col];
                float v1 = acc[mt][nt][half * 2 + 1] + bsm[col + 1];
                if (DO_SILU) {
                    v0 = v0 / (1.f + __expf(-v0));
                    v1 = v1 / (1.f + __expf(-v1));
                    uint32_t p = (uint32_t)__half_as_ushort(__float2half_rn(v0))
                               | ((uint32_t)__half_as_ushort(__float2half_rn(v1)) << 16);
                    *(uint32_t*)(O16 + (size_t)orow * NDIM + n0 + col) = p;
                } else {
                    float2 v = make_float2(v0, v1);
                    *(float2*)(Of + (size_t)orow * NDIM + n0 + col) = v;
                }
            }
        }
}

// ---------------------------------------------------------------------------
// Launch: inputs: x, central_species, W1, b1, W2, b2
// ---------------------------------------------------------------------------
extern "C" void kernel_launch(void* const* d_in, const int* in_sizes, int n_in,
                              void* d_out, int out_size)
{
    const float* x   = (const float*)d_in[0];
    const int*   spw = (const int*)d_in[1];
    const float* W1  = (const float*)d_in[2];
    const float* b1  = (const float*)d_in[3];
    const float* W2  = (const float*)d_in[4];
    const float* b2  = (const float*)d_in[5];
    float*       out = (float*)d_out;

    __half *x16, *H16, *w1, *w2;
    cudaGetSymbolAddress((void**)&x16, g_x16);
    cudaGetSymbolAddress((void**)&H16, g_H16);
    cudaGetSymbolAddress((void**)&w1,  g_w1);
    cudaGetSymbolAddress((void**)&w2,  g_w2);

    cudaFuncSetAttribute(moe_gemm<DIN,  DHID, true,  false, true>,
                         cudaFuncAttributeMaxDynamicSharedMemorySize, GEMM_SMEM);
    cudaFuncSetAttribute(moe_gemm<DHID, DOUT, false, true,  false>,
                         cudaFuncAttributeMaxDynamicSharedMemorySize, GEMM_SMEM);

    k_reset  <<<1, 32>>>();
    k_probe  <<<128, 256>>>(spw);
    k_scatter<<<NT / 256, 256>>>(spw);
    k_prefix <<<1, 1>>>();

    conv_x<<<NT * DIN / 4 / 256, 256>>>(x);
    conv_w<DIN,  DHID><<<dim3(DIN / 32,  DHID / 32, NSPEC), dim3(32, 8)>>>(W1, w1);
    conv_w<DHID, DOUT><<<dim3(DHID / 32, DOUT / 32, NSPEC), dim3(32, 8)>>>(W2, w2);

    // GEMM1: H = silu(x @ W1[s] + b1[s]) -> compact fp16
    moe_gemm<DIN, DHID, true, false, true>
        <<<dim3(NT / 128, DHID / 128, NSPEC), 256, GEMM_SMEM>>>(
            x16, w1, b1, H16, nullptr);

    // GEMM2: out = H @ W2[s] + b2[s] -> scatter fp32 by token
    moe_gemm<DHID, DOUT, false, true, false>
        <<<dim3(NT / 128, DOUT / 128, NSPEC), 256, GEMM_SMEM>>>(
            H16, w2, b2, nullptr, out);
}

// round 10
// speedup vs baseline: 6.6497x; 1.0469x over previous
#include <cuda_runtime.h>
#include <cuda_fp16.h>
#include <stdint.h>
#include <math.h>

#define NT    65536
#define NSPEC 4
#define DIN   256
#define DHID  1024
#define DOUT  256
#define MT    192            // max m-tiles per species (24576 rows capacity)

// ---------------------------------------------------------------------------
// Device-global scratch (allocation-free rule).
// ---------------------------------------------------------------------------
__device__ int g_cnt[NSPEC];
__device__ int g_or_odd;
__device__ int g_idx[NSPEC * NT];
__device__ __half g_x16[(size_t)NT * DIN];
__device__ __half g_H16[(size_t)NT * DHID];
__device__ __half g_w1[(size_t)NSPEC * DHID * DIN];   // [s][n][k] fp16
__device__ __half g_w2[(size_t)NSPEC * DOUT * DHID];

// ---------------------------------------------------------------------------
// Helpers
// ---------------------------------------------------------------------------
__device__ __forceinline__ uint32_t s2u(const void* p) {
    uint32_t a;
    asm("{ .reg .u64 t; cvta.to.shared.u64 t, %1; cvt.u32.u64 %0, t; }" : "=r"(a) : "l"(p));
    return a;
}
__device__ __forceinline__ uint32_t swz(uint32_t o) { return o ^ ((o >> 3) & 0x70u); }

#define CP_COMMIT() asm volatile("cp.async.commit_group;" ::: "memory")
template<int N> __device__ __forceinline__ void cp_wait() {
    asm volatile("cp.async.wait_group %0;" :: "n"(N) : "memory");
}
__device__ __forceinline__ void cp16z(uint32_t dst, const void* src, unsigned sz) {
    asm volatile("cp.async.cg.shared.global [%0], [%1], 16, %2;"
                 :: "r"(dst), "l"(src), "r"(sz) : "memory");
}

#define LDM4(r, a) \
    asm volatile("ldmatrix.sync.aligned.m8n8.x4.shared.b16 {%0,%1,%2,%3}, [%4];" \
                 : "=r"((r)[0]), "=r"((r)[1]), "=r"((r)[2]), "=r"((r)[3]) : "r"(a))

#define MMA(c, a, b) \
    asm volatile("mma.sync.aligned.m16n8k16.row.col.f32.f16.f16.f32 " \
                 "{%0,%1,%2,%3},{%4,%5,%6,%7},{%8,%9},{%0,%1,%2,%3};" \
                 : "+f"((c)[0]), "+f"((c)[1]), "+f"((c)[2]), "+f"((c)[3]) \
                 : "r"((a)[0]), "r"((a)[1]), "r"((a)[2]), "r"((a)[3]), \
                   "r"((b)[0]), "r"((b)[1]))

// ---------------------------------------------------------------------------
// conv_x + counter reset (stream order guarantees reset precedes probe/scatter)
// ---------------------------------------------------------------------------
__global__ void conv_x(const float* __restrict__ x) {
    if (blockIdx.x == 0 && threadIdx.x < NSPEC + 1) {
        if (threadIdx.x < NSPEC) g_cnt[threadIdx.x] = 0;
        else                     g_or_odd = 0;
    }
    size_t i = ((size_t)blockIdx.x * 256 + threadIdx.x) * 4;
    float4 v = *(const float4*)(x + i);
    uint2 p;
    p.x = (uint32_t)__half_as_ushort(__float2half_rn(v.x))
        | ((uint32_t)__half_as_ushort(__float2half_rn(v.y)) << 16);
    p.y = (uint32_t)__half_as_ushort(__float2half_rn(v.z))
        | ((uint32_t)__half_as_ushort(__float2half_rn(v.w)) << 16);
    ((uint2*)g_x16)[i / 4] = p;
}

// Species dtype probe (JAX x64-off silently emits int32): if int64 w/ values
// 0..3, every odd 32-bit word is 0; random int32 0..3 fails that w.h.p.
__global__ void k_probe(const int* __restrict__ w) {
    int i = blockIdx.x * blockDim.x + threadIdx.x;   // odd-word index 0..32767
    int v = w[2 * i + 1];
    for (int o = 16; o > 0; o >>= 1) v |= __shfl_xor_sync(0xffffffffu, v, o);
    if ((threadIdx.x & 31) == 0 && v) atomicOr(&g_or_odd, 1);
}
__global__ void k_scatter(const int* __restrict__ w) {
    int i = blockIdx.x * blockDim.x + threadIdx.x;
    if (i >= NT) return;
    bool is64 = (g_or_odd == 0);
    int s = is64 ? w[2 * i] : w[i];
    if ((unsigned)s < NSPEC) {
        int p = atomicAdd(&g_cnt[s], 1);
        g_idx[s * NT + p] = i;
    }
}

// ---------------------------------------------------------------------------
// Merged weight transpose+convert: W1 blocks [0,1024), W2 blocks [1024,2048)
// ---------------------------------------------------------------------------
__global__ void conv_w_all(const float* __restrict__ W1, const float* __restrict__ W2) {
    __shared__ float sm[32][33];
    int id = blockIdx.x;
    const float* W; __half* T; int KD, ND, k0, n0, s;
    if (id < 1024) {            // W1: KD=256 (8 k-tiles), ND=1024 (32 n-tiles)
        W = W1; T = g_w1; KD = DIN; ND = DHID;
        k0 = (id & 7) * 32; n0 = ((id >> 3) & 31) * 32; s = id >> 8;
    } else {                    // W2: KD=1024 (32 k-tiles), ND=256 (8 n-tiles)
        int j = id - 1024;
        W = W2; T = g_w2; KD = DHID; ND = DOUT;
        k0 = (j & 31) * 32; n0 = ((j >> 5) & 7) * 32; s = j >> 8;
    }
    int tx = threadIdx.x, ty = threadIdx.y;   // (32, 8)
    const float* Wp = W + (size_t)s * KD * ND;
#pragma unroll
    for (int j = 0; j < 4; j++)
        sm[ty + j * 8][tx] = Wp[(size_t)(k0 + ty + j * 8) * ND + n0 + tx];
    __syncthreads();
#pragma unroll
    for (int j = 0; j < 4; j++) {
        int n = ty + j * 8;
        T[((size_t)s * ND + n0 + n) * KD + k0 + tx] = __float2half_rn(sm[tx][n]);
    }
}

// ---------------------------------------------------------------------------
// mma.sync fp16 GEMM over one species bucket (single-pass fp16).
//   Block tile 128(M) x 128(N), K chunks of 64. 8 warps: warp tile 64x32.
//   3-stage cp.async pipeline, ONE __syncthreads per chunk, occupancy 2.
// Dynamic SMEM: 3 stages x 32KB (A 16K | B 16K), SW128-swizzled 128B rows.
// ---------------------------------------------------------------------------
#define GEMM_SMEM 98304

template<int KT, int NDIM, bool GATHER_A, bool SCATTER_OUT, bool DO_SILU>
__global__ void __launch_bounds__(256, 2)
moe_gemm(const __half* __restrict__ A, const __half* __restrict__ B,
         const float* __restrict__ bias,
         __half* __restrict__ O16, float* __restrict__ Of)
{
    constexpr int NC = KT / 64;
    extern __shared__ char dyn[];
    __shared__ int   tok[128];
    __shared__ float bsm[128];

    const int tid = threadIdx.x, wid = tid >> 5, lane = tid & 31;
    const int s   = blockIdx.z;
    const int cnt = g_cnt[s];
    const int m0  = blockIdx.x * 128;
    if (m0 >= cnt) return;
    const int n0    = blockIdx.y * 128;
    const int valid = min(128, cnt - m0);
    int off = 0;                               // compact offset (replaces k_prefix)
#pragma unroll
    for (int t = 0; t < NSPEC; t++) if (t < s) off += g_cnt[t];
    const uint32_t sbase = s2u(dyn);

    for (int i = tid; i < 128; i += 256)
        tok[i] = (i < valid) ? g_idx[s * NT + m0 + i] : -1;
    if (tid < 128) bsm[tid] = bias[(size_t)s * NDIM + n0 + tid];
    __syncthreads();

    auto issue = [&](int c) {
        const int k0 = c * 64;
        const uint32_t bb = sbase + (uint32_t)(c % 3) * 32768u;
#pragma unroll
        for (int i = 0; i < 4; i++) {          // A: 128 rows x 8 units
            int t = tid + i * 256;
            int row = t >> 3, u = t & 7;
            int gr;
            if (GATHER_A) gr = tok[row];
            else          gr = (row < valid) ? (off + m0 + row) : -1;
            const __half* src = A + (size_t)max(gr, 0) * KT + k0 + u * 8;
            uint32_t dst = bb + swz((uint32_t)row * 128u + u * 16u);
            cp16z(dst, src, (gr >= 0) ? 16u : 0u);
        }
#pragma unroll
        for (int i = 0; i < 4; i++) {          // B: 128 rows x 8 units
            int t = tid + i * 256;
            int row = t >> 3, u = t & 7;
            const __half* src = B + ((size_t)s * NDIM + n0 + row) * KT + k0 + u * 8;
            uint32_t dst = bb + 16384u + swz((uint32_t)row * 128u + u * 16u);
            cp16z(dst, src, 16u);
        }
        CP_COMMIT();
    };

    float acc[4][4][4];
#pragma unroll
    for (int a = 0; a < 4; a++)
#pragma unroll
        for (int b = 0; b < 4; b++)
#pragma unroll
            for (int q = 0; q < 4; q++) acc[a][b][q] = 0.f;

    const int wm = wid & 1;            // M warp (0-1): 64 rows each
    const int wn = wid >> 1;           // N warp (0-3): 32 cols each
    const int ra = (lane & 7) + ((lane >> 3) & 1) * 8;
    const int ca = ((lane >> 4) & 1) * 8;
    const int rb = (lane & 7) + ((lane >> 4) & 1) * 8;
    const int cb = ((lane >> 3) & 1) * 8;

    issue(0);
    if (NC > 1) issue(1);
#pragma unroll 1
    for (int c = 0; c < NC; c++) {
        if (c + 1 < NC) cp_wait<1>();          // chunk c landed
        else            cp_wait<0>();
        __syncthreads();                       // all warps done reading c-1
        if (c + 2 < NC) issue(c + 2);          // writes (c+2)%3 != c%3: safe
        const uint32_t bb = sbase + (uint32_t)(c % 3) * 32768u;
#pragma unroll
        for (int ks = 0; ks < 4; ks++) {
            uint32_t af[4][4], bf[2][4];
#pragma unroll
            for (int mt = 0; mt < 4; mt++) {
                uint32_t o = (uint32_t)((wm * 64 + mt * 16 + ra) * 128
                                        + (ks * 16 + ca) * 2);
                LDM4(af[mt], bb + swz(o));
            }
#pragma unroll
            for (int np = 0; np < 2; np++) {
                uint32_t o = (uint32_t)((wn * 32 + np * 16 + rb) * 128
                                        + (ks * 16 + cb) * 2);
                LDM4(bf[np], bb + 16384u + swz(o));
            }
#pragma unroll
            for (int mt = 0; mt < 4; mt++)
#pragma unroll
                for (int nt = 0; nt < 4; nt++)
                    MMA(acc[mt][nt], af[mt], &bf[nt >> 1][(nt & 1) * 2]);
        }
    }

    // Epilogue: bias (+SiLU) and store. Row = wm*64+mt*16+gid(+8),
    // col = wn*32+nt*8+tig*2.
    const int gid = lane >> 2, tig = lane & 3;
#pragma unroll
    for (int mt = 0; mt < 4; mt++)
#pragma unroll
        for (int half = 0; half < 2; half++) {
            int lrow = wm * 64 + mt * 16 + gid + half * 8;
            if (lrow >= valid) continue;
            int orow = SCATTER_OUT ? tok[lrow] : (off + m0 + lrow);
#pragma unroll
            for (int nt = 0; nt < 4; nt++) {
                int col = wn * 32 + nt * 8 + tig * 2;
                float v0 = acc[mt][nt][half * 2 + 0] + bsm[col];
                float v1 = acc[mt][nt][half * 2 + 1] + bsm[col + 1];
                if (DO_SILU) {
                    v0 = v0 / (1.f + __expf(-v0));
                    v1 = v1 / (1.f + __expf(-v1));
                    uint32_t p = (uint32_t)__half_as_ushort(__float2half_rn(v0))
                               | ((uint32_t)__half_as_ushort(__float2half_rn(v1)) << 16);
                    *(uint32_t*)(O16 + (size_t)orow * NDIM + n0 + col) = p;
                } else {
                    float2 v = make_float2(v0, v1);
                    *(float2*)(Of + (size_t)orow * NDIM + n0 + col) = v;
                }
            }
        }
}

// ---------------------------------------------------------------------------
// Launch: inputs: x, central_species, W1, b1, W2, b2
// ---------------------------------------------------------------------------
extern "C" void kernel_launch(void* const* d_in, const int* in_sizes, int n_in,
                              void* d_out, int out_size)
{
    const float* x   = (const float*)d_in[0];
    const int*   spw = (const int*)d_in[1];
    const float* W1  = (const float*)d_in[2];
    const float* b1  = (const float*)d_in[3];
    const float* W2  = (const float*)d_in[4];
    const float* b2  = (const float*)d_in[5];
    float*       out = (float*)d_out;

    __half *x16, *H16, *w1, *w2;
    cudaGetSymbolAddress((void**)&x16, g_x16);
    cudaGetSymbolAddress((void**)&H16, g_H16);
    cudaGetSymbolAddress((void**)&w1,  g_w1);
    cudaGetSymbolAddress((void**)&w2,  g_w2);

    cudaFuncSetAttribute(moe_gemm<DIN,  DHID, true,  false, true>,
                         cudaFuncAttributeMaxDynamicSharedMemorySize, GEMM_SMEM);
    cudaFuncSetAttribute(moe_gemm<DHID, DOUT, false, true,  false>,
                         cudaFuncAttributeMaxDynamicSharedMemorySize, GEMM_SMEM);

    conv_x    <<<NT * DIN / 4 / 256, 256>>>(x);       // + counter reset
    k_probe   <<<128, 256>>>(spw);
    k_scatter <<<NT / 256, 256>>>(spw);
    conv_w_all<<<2048, dim3(32, 8)>>>(W1, W2);

    // GEMM1: H = silu(x @ W1[s] + b1[s]) -> compact fp16
    moe_gemm<DIN, DHID, true, false, true>
        <<<dim3(MT, DHID / 128, NSPEC), 256, GEMM_SMEM>>>(
            x16, w1, b1, H16, nullptr);

    // GEMM2: out = H @ W2[s] + b2[s] -> scatter fp32 by token
    moe_gemm<DHID, DOUT, false, true, false>
        <<<dim3(MT, DOUT / 128, NSPEC), 256, GEMM_SMEM>>>(
            H16, w2, b2, nullptr, out);
}

// round 11
// speedup vs baseline: 6.8387x; 1.0284x over previous
#include <cuda_runtime.h>
#include <cuda_fp16.h>
#include <stdint.h>
#include <math.h>

#define NT    65536
#define NSPEC 4
#define DIN   256
#define DHID  1024
#define DOUT  256
#define MT    192            // max m-tiles per species (24576 rows capacity)

// ---------------------------------------------------------------------------
// Device-global scratch (allocation-free rule).
// ---------------------------------------------------------------------------
__device__ int g_cnt[NSPEC];
__device__ int g_or_odd;
__device__ int g_idx[NSPEC * NT];
__device__ __half g_x16[(size_t)NT * DIN];
__device__ __half g_H16[(size_t)NT * DHID];
__device__ __half g_w1[(size_t)NSPEC * DHID * DIN];   // [s][n][k] fp16
__device__ __half g_w2[(size_t)NSPEC * DOUT * DHID];

// ---------------------------------------------------------------------------
// Helpers
// ---------------------------------------------------------------------------
__device__ __forceinline__ uint32_t s2u(const void* p) {
    uint32_t a;
    asm("{ .reg .u64 t; cvta.to.shared.u64 t, %1; cvt.u32.u64 %0, t; }" : "=r"(a) : "l"(p));
    return a;
}
__device__ __forceinline__ uint32_t swz(uint32_t o) { return o ^ ((o >> 3) & 0x70u); }

#define CP_COMMIT() asm volatile("cp.async.commit_group;" ::: "memory")
template<int N> __device__ __forceinline__ void cp_wait() {
    asm volatile("cp.async.wait_group %0;" :: "n"(N) : "memory");
}
__device__ __forceinline__ void cp16z(uint32_t dst, const void* src, unsigned sz) {
    asm volatile("cp.async.cg.shared.global [%0], [%1], 16, %2;"
                 :: "r"(dst), "l"(src), "r"(sz) : "memory");
}

#define LDM4(r, a) \
    asm volatile("ldmatrix.sync.aligned.m8n8.x4.shared.b16 {%0,%1,%2,%3}, [%4];" \
                 : "=r"((r)[0]), "=r"((r)[1]), "=r"((r)[2]), "=r"((r)[3]) : "r"(a))

#define MMA(c, a, b) \
    asm volatile("mma.sync.aligned.m16n8k16.row.col.f32.f16.f16.f32 " \
                 "{%0,%1,%2,%3},{%4,%5,%6,%7},{%8,%9},{%0,%1,%2,%3};" \
                 : "+f"((c)[0]), "+f"((c)[1]), "+f"((c)[2]), "+f"((c)[3]) \
                 : "r"((a)[0]), "r"((a)[1]), "r"((a)[2]), "r"((a)[3]), \
                   "r"((b)[0]), "r"((b)[1]))

// ---------------------------------------------------------------------------
// conv_x + counter resets (block 0). Stream order guarantees the resets
// complete before k_probe / k_scatter atomics run.
// ---------------------------------------------------------------------------
__global__ void conv_x(const float* __restrict__ x) {
    if (blockIdx.x == 0 && threadIdx.x < NSPEC + 1) {
        if (threadIdx.x < NSPEC) g_cnt[threadIdx.x] = 0;
        else                     g_or_odd = 0;
    }
    size_t i = ((size_t)blockIdx.x * 256 + threadIdx.x) * 4;
    float4 v = *(const float4*)(x + i);
    uint2 p;
    p.x = (uint32_t)__half_as_ushort(__float2half_rn(v.x))
        | ((uint32_t)__half_as_ushort(__float2half_rn(v.y)) << 16);
    p.y = (uint32_t)__half_as_ushort(__float2half_rn(v.z))
        | ((uint32_t)__half_as_ushort(__float2half_rn(v.w)) << 16);
    ((uint2*)g_x16)[i / 4] = p;
}

// Species dtype probe (JAX x64-off silently emits int32): if int64 with
// values 0..3, every odd 32-bit word is 0; random int32 0..3 has a nonzero
// odd word w.p. 1 - 4^-2048. Single block, 2048 odd words (all within the
// 65536-word region that is safe under both layouts).
__global__ void k_probe(const int* __restrict__ w) {
    int v = 0;
#pragma unroll
    for (int j = 0; j < 8; j++)
        v |= w[2 * (threadIdx.x + j * 256) + 1];
    for (int o = 16; o > 0; o >>= 1) v |= __shfl_xor_sync(0xffffffffu, v, o);
    if ((threadIdx.x & 31) == 0 && v) atomicOr(&g_or_odd, 1);
}

// Warp-aggregated scatter: one atomic per (warp, species) instead of one
// per token. Bucket order differs run-to-run but per-token output does not.
__global__ void k_scatter(const int* __restrict__ w) {
    int i = blockIdx.x * blockDim.x + threadIdx.x;
    if (i >= NT) return;
    const int lane = threadIdx.x & 31;
    bool is64 = (g_or_odd == 0);
    int s = is64 ? w[2 * i] : w[i];
#pragma unroll
    for (int t = 0; t < NSPEC; t++) {
        unsigned m = __ballot_sync(0xffffffffu, s == t);
        if (s == t) {
            int leader = __ffs(m) - 1;
            int rank   = __popc(m & ((1u << lane) - 1u));
            int base   = 0;
            if (lane == leader) base = atomicAdd(&g_cnt[t], __popc(m));
            base = __shfl_sync(m, base, leader);
            g_idx[t * NT + base + rank] = i;
        }
    }
}

// ---------------------------------------------------------------------------
// Merged weight transpose+convert: W1 blocks [0,1024), W2 blocks [1024,2048)
// ---------------------------------------------------------------------------
__global__ void conv_w_all(const float* __restrict__ W1, const float* __restrict__ W2) {
    __shared__ float sm[32][33];
    int id = blockIdx.x;
    const float* W; __half* T; int KD, ND, k0, n0, s;
    if (id < 1024) {            // W1: KD=256 (8 k-tiles), ND=1024 (32 n-tiles)
        W = W1; T = g_w1; KD = DIN; ND = DHID;
        k0 = (id & 7) * 32; n0 = ((id >> 3) & 31) * 32; s = id >> 8;
    } else {                    // W2: KD=1024 (32 k-tiles), ND=256 (8 n-tiles)
        int j = id - 1024;
        W = W2; T = g_w2; KD = DHID; ND = DOUT;
        k0 = (j & 31) * 32; n0 = ((j >> 5) & 7) * 32; s = j >> 8;
    }
    int tx = threadIdx.x, ty = threadIdx.y;   // (32, 8)
    const float* Wp = W + (size_t)s * KD * ND;
#pragma unroll
    for (int j = 0; j < 4; j++)
        sm[ty + j * 8][tx] = Wp[(size_t)(k0 + ty + j * 8) * ND + n0 + tx];
    __syncthreads();
#pragma unroll
    for (int j = 0; j < 4; j++) {
        int n = ty + j * 8;
        T[((size_t)s * ND + n0 + n) * KD + k0 + tx] = __float2half_rn(sm[tx][n]);
    }
}

// ---------------------------------------------------------------------------
// mma.sync fp16 GEMM over one species bucket (single-pass fp16).
//   Block tile 128(M) x 128(N), K chunks of 64. 8 warps: warp tile 64x32.
//   3-stage cp.async pipeline, ONE __syncthreads per chunk, occupancy 2.
// Dynamic SMEM: 3 stages x 32KB (A 16K | B 16K), SW128-swizzled 128B rows.
// ---------------------------------------------------------------------------
#define GEMM_SMEM 98304

template<int KT, int NDIM, bool GATHER_A, bool SCATTER_OUT, bool DO_SILU>
__global__ void __launch_bounds__(256, 2)
moe_gemm(const __half* __restrict__ A, const __half* __restrict__ B,
         const float* __restrict__ bias,
         __half* __restrict__ O16, float* __restrict__ Of)
{
    constexpr int NC = KT / 64;
    extern __shared__ char dyn[];
    __shared__ int   tok[128];
    __shared__ float bsm[128];

    const int tid = threadIdx.x, wid = tid >> 5, lane = tid & 31;
    const int s   = blockIdx.z;
    const int cnt = g_cnt[s];
    const int m0  = blockIdx.x * 128;
    if (m0 >= cnt) return;
    const int n0    = blockIdx.y * 128;
    const int valid = min(128, cnt - m0);
    int off = 0;                               // compact offset
#pragma unroll
    for (int t = 0; t < NSPEC; t++) if (t < s) off += g_cnt[t];
    const uint32_t sbase = s2u(dyn);

    for (int i = tid; i < 128; i += 256)
        tok[i] = (i < valid) ? g_idx[s * NT + m0 + i] : -1;
    if (tid < 128) bsm[tid] = bias[(size_t)s * NDIM + n0 + tid];
    __syncthreads();

    auto issue = [&](int c) {
        const int k0 = c * 64;
        const uint32_t bb = sbase + (uint32_t)(c % 3) * 32768u;
#pragma unroll
        for (int i = 0; i < 4; i++) {          // A: 128 rows x 8 units
            int t = tid + i * 256;
            int row = t >> 3, u = t & 7;
            int gr;
            if (GATHER_A) gr = tok[row];
            else          gr = (row < valid) ? (off + m0 + row) : -1;
            const __half* src = A + (size_t)max(gr, 0) * KT + k0 + u * 8;
            uint32_t dst = bb + swz((uint32_t)row * 128u + u * 16u);
            cp16z(dst, src, (gr >= 0) ? 16u : 0u);
        }
#pragma unroll
        for (int i = 0; i < 4; i++) {          // B: 128 rows x 8 units
            int t = tid + i * 256;
            int row = t >> 3, u = t & 7;
            const __half* src = B + ((size_t)s * NDIM + n0 + row) * KT + k0 + u * 8;
            uint32_t dst = bb + 16384u + swz((uint32_t)row * 128u + u * 16u);
            cp16z(dst, src, 16u);
        }
        CP_COMMIT();
    };

    float acc[4][4][4];
#pragma unroll
    for (int a = 0; a < 4; a++)
#pragma unroll
        for (int b = 0; b < 4; b++)
#pragma unroll
            for (int q = 0; q < 4; q++) acc[a][b][q] = 0.f;

    const int wm = wid & 1;            // M warp (0-1): 64 rows each
    const int wn = wid >> 1;           // N warp (0-3): 32 cols each
    const int ra = (lane & 7) + ((lane >> 3) & 1) * 8;
    const int ca = ((lane >> 4) & 1) * 8;
    const int rb = (lane & 7) + ((lane >> 4) & 1) * 8;
    const int cb = ((lane >> 3) & 1) * 8;

    issue(0);
    if (NC > 1) issue(1);
#pragma unroll 1
    for (int c = 0; c < NC; c++) {
        if (c + 1 < NC) cp_wait<1>();          // chunk c landed
        else            cp_wait<0>();
        __syncthreads();                       // all warps done reading c-1
        if (c + 2 < NC) issue(c + 2);          // writes (c+2)%3 != c%3: safe
        const uint32_t bb = sbase + (uint32_t)(c % 3) * 32768u;
#pragma unroll
        for (int ks = 0; ks < 4; ks++) {
            uint32_t af[4][4], bf[2][4];
#pragma unroll
            for (int mt = 0; mt < 4; mt++) {
                uint32_t o = (uint32_t)((wm * 64 + mt * 16 + ra) * 128
                                        + (ks * 16 + ca) * 2);
                LDM4(af[mt], bb + swz(o));
            }
#pragma unroll
            for (int np = 0; np < 2; np++) {
                uint32_t o = (uint32_t)((wn * 32 + np * 16 + rb) * 128
                                        + (ks * 16 + cb) * 2);
                LDM4(bf[np], bb + 16384u + swz(o));
            }
#pragma unroll
            for (int mt = 0; mt < 4; mt++)
#pragma unroll
                for (int nt = 0; nt < 4; nt++)
                    MMA(acc[mt][nt], af[mt], &bf[nt >> 1][(nt & 1) * 2]);
        }
    }

    // Epilogue: bias (+SiLU) and store.
    const int gid = lane >> 2, tig = lane & 3;
#pragma unroll
    for (int mt = 0; mt < 4; mt++)
#pragma unroll
        for (int half = 0; half < 2; half++) {
            int lrow = wm * 64 + mt * 16 + gid + half * 8;
            if (lrow >= valid) continue;
            int orow = SCATTER_OUT ? tok[lrow] : (off + m0 + lrow);
#pragma unroll
            for (int nt = 0; nt < 4; nt++) {
                int col = wn * 32 + nt * 8 + tig * 2;
                float v0 = acc[mt][nt][half * 2 + 0] + bsm[col];
                float v1 = acc[mt][nt][half * 2 + 1] + bsm[col + 1];
                if (DO_SILU) {
                    v0 = v0 / (1.f + __expf(-v0));
                    v1 = v1 / (1.f + __expf(-v1));
                    uint32_t p = (uint32_t)__half_as_ushort(__float2half_rn(v0))
                               | ((uint32_t)__half_as_ushort(__float2half_rn(v1)) << 16);
                    *(uint32_t*)(O16 + (size_t)orow * NDIM + n0 + col) = p;
                } else {
                    float2 v = make_float2(v0, v1);
                    *(float2*)(Of + (size_t)orow * NDIM + n0 + col) = v;
                }
            }
        }
}

// ---------------------------------------------------------------------------
// Launch. Weight conversion is independent of the x/species chain, so it is
// forked onto a side stream (event fork/join — graph-capture legal) and
// overlaps conv_x + probe + scatter.
// ---------------------------------------------------------------------------
extern "C" void kernel_launch(void* const* d_in, const int* in_sizes, int n_in,
                              void* d_out, int out_size)
{
    const float* x   = (const float*)d_in[0];
    const int*   spw = (const int*)d_in[1];
    const float* W1  = (const float*)d_in[2];
    const float* b1  = (const float*)d_in[3];
    const float* W2  = (const float*)d_in[4];
    const float* b2  = (const float*)d_in[5];
    float*       out = (float*)d_out;

    __half *x16, *H16, *w1, *w2;
    cudaGetSymbolAddress((void**)&x16, g_x16);
    cudaGetSymbolAddress((void**)&H16, g_H16);
    cudaGetSymbolAddress((void**)&w1,  g_w1);
    cudaGetSymbolAddress((void**)&w2,  g_w2);

    static cudaStream_t side = nullptr;
    static cudaEvent_t  evF = nullptr, evJ = nullptr;
    if (!side) {
        cudaStreamCreateWithFlags(&side, cudaStreamNonBlocking);
        cudaEventCreateWithFlags(&evF, cudaEventDisableTiming);
        cudaEventCreateWithFlags(&evJ, cudaEventDisableTiming);
        cudaFuncSetAttribute(moe_gemm<DIN,  DHID, true,  false, true>,
                             cudaFuncAttributeMaxDynamicSharedMemorySize, GEMM_SMEM);
        cudaFuncSetAttribute(moe_gemm<DHID, DOUT, false, true,  false>,
                             cudaFuncAttributeMaxDynamicSharedMemorySize, GEMM_SMEM);
    }

    // Fork: conv_w_all runs concurrently with the x/species chain.
    cudaEventRecord(evF, 0);
    cudaStreamWaitEvent(side, evF, 0);
    conv_w_all<<<2048, dim3(32, 8), 0, side>>>(W1, W2);
    cudaEventRecord(evJ, side);

    conv_x   <<<NT * DIN / 4 / 256, 256>>>(x);   // + counter resets
    k_probe  <<<1, 256>>>(spw);
    k_scatter<<<NT / 256, 256>>>(spw);

    // Join before GEMM1 (needs w1).
    cudaStreamWaitEvent(0, evJ, 0);

    // GEMM1: H = silu(x @ W1[s] + b1[s]) -> compact fp16
    moe_gemm<DIN, DHID, true, false, true>
        <<<dim3(MT, DHID / 128, NSPEC), 256, GEMM_SMEM>>>(
            x16, w1, b1, H16, nullptr);

    // GEMM2: out = H @ W2[s] + b2[s] -> scatter fp32 by token
    moe_gemm<DHID, DOUT, false, true, false>
        <<<dim3(MT, DOUT / 128, NSPEC), 256, GEMM_SMEM>>>(
            H16, w2, b2, nullptr, out);
}